// round 1
// baseline (speedup 1.0000x reference)
#include <cuda_runtime.h>
#include <cuda_bf16.h>
#include <math.h>

// ---------------- problem constants ----------------
#define NB    2
#define NG    4
#define NBG   8          // NB*NG
#define PQ    1024       // 4*16*16
#define PJ    128        // 2*8*8
#define CG    64         // DIM/GROUPS
#define OFFD  128
#define CPB   64

// ---------------- scratch ----------------
__device__ float g_q[NBG * 128 * PQ];     // [bg][o][p]
__device__ float g_dw[NBG * 128 * PJ];    // [bg][c][j]  (gelu(dwconv) output)
__device__ float g_grid[NBG * PJ * 3];    // [bg][j][3]  normalized coords (f,h,w)
__device__ float g_kv[NBG * CG * PJ];     // [bg][i][j]
__device__ float g_k[NBG * 128 * PJ];     // [bg][o][j]
__device__ float g_v[NBG * 128 * PJ];
__device__ float g_att[NB * 512 * PQ];    // [b][c][p]

// ---------------- f32x2 helpers (Blackwell packed fp32) ----------------
__device__ __forceinline__ unsigned long long pk2(float lo, float hi) {
    unsigned long long r;
    asm("mov.b64 %0, {%1, %2};" : "=l"(r) : "f"(lo), "f"(hi));
    return r;
}
__device__ __forceinline__ void upk2(unsigned long long v, float& lo, float& hi) {
    asm("mov.b64 {%0, %1}, %2;" : "=f"(lo), "=f"(hi) : "l"(v));
}
__device__ __forceinline__ unsigned long long ffma2(unsigned long long a,
                                                    unsigned long long b,
                                                    unsigned long long c) {
    unsigned long long d;
    asm("fma.rn.f32x2 %0, %1, %2, %3;" : "=l"(d) : "l"(a), "l"(b), "l"(c));
    return d;
}

// ---------------- K1: grouped 1x1 conv -> q ----------------
__global__ void __launch_bounds__(128) k_q(const float* __restrict__ x,
                                           const float* __restrict__ wq) {
    __shared__ float sw[128 * 64];
    int bg = blockIdx.x;          // 0..7
    int pt = blockIdx.y;          // 0..7
    int b = bg >> 2, g = bg & 3;
    int tid = threadIdx.x;
    for (int t = tid; t < 128 * 64; t += 128) sw[t] = wq[g * 128 * 64 + t];
    __syncthreads();
    int p = pt * 128 + tid;
    float xr[64];
#pragma unroll
    for (int i = 0; i < 64; i++) xr[i] = x[(b * 256 + g * 64 + i) * 1024 + p];
    for (int o = 0; o < 128; o++) {
        float acc = 0.f;
#pragma unroll
        for (int i = 0; i < 64; i++) acc = fmaf(xr[i], sw[o * 64 + i], acc);
        g_q[(bg * 128 + o) * 1024 + p] = acc;
    }
}

// ---------------- K2: depthwise strided conv + bias + exact GELU ----------------
__global__ void __launch_bounds__(256) k_dw(const float* __restrict__ w,
                                            const float* __restrict__ bias) {
    int idx = blockIdx.x * blockDim.x + threadIdx.x;  // NBG*128*128
    if (idx >= NBG * 128 * PJ) return;
    int j = idx & 127;
    int c = (idx >> 7) & 127;
    int bg = idx >> 14;
    int zo = j >> 6, yo = (j >> 3) & 7, xo = j & 7;
    const float* qb = g_q + (bg * 128 + c) * 1024;
    const float* wc = w + c * 64;
    float acc = 0.f;
#pragma unroll
    for (int kz = 0; kz < 4; kz++) {
        int zi = zo * 2 - 1 + kz;
        if (zi < 0 || zi >= 4) continue;
#pragma unroll
        for (int ky = 0; ky < 4; ky++) {
            int yi = yo * 2 - 1 + ky;
            if (yi < 0 || yi >= 16) continue;
#pragma unroll
            for (int kx = 0; kx < 4; kx++) {
                int xi = xo * 2 - 1 + kx;
                if (xi < 0 || xi >= 16) continue;
                acc = fmaf(qb[(zi * 16 + yi) * 16 + xi], wc[(kz * 4 + ky) * 4 + kx], acc);
            }
        }
    }
    acc += bias[c];
    float ge = 0.5f * acc * (1.f + erff(acc * 0.70710678118654752f));
    g_dw[idx] = ge;
}

// ---------------- K3: pointwise -> tanh -> scaled offsets -> normalized grid ----------------
__global__ void __launch_bounds__(256) k_off(const float* __restrict__ pw) {
    int idx = blockIdx.x * blockDim.x + threadIdx.x;  // NBG*PJ
    if (idx >= NBG * PJ) return;
    int j = idx & 127;
    int bg = idx >> 7;
    float a0 = 0.f, a1 = 0.f, a2 = 0.f;
    for (int c = 0; c < 128; c++) {
        float v = g_dw[(bg * 128 + c) * 128 + j];
        a0 = fmaf(v, pw[c], a0);
        a1 = fmaf(v, pw[128 + c], a1);
        a2 = fmaf(v, pw[256 + c], a2);
    }
    float o0 = tanhf(a0) * 2.f, o1 = tanhf(a1) * 2.f, o2 = tanhf(a2) * 2.f;
    int fz = j >> 6, hy = (j >> 3) & 7, wx = j & 7;
    float v0 = (float)fz + o0, v1 = (float)hy + o1, v2 = (float)wx + o2;
    // norm_coords with sizes (2,8,8) -> divisors (1,7,7)
    g_grid[idx * 3 + 0] = 2.f * v0 - 1.f;
    g_grid[idx * 3 + 1] = 2.f * v1 / 7.f - 1.f;
    g_grid[idx * 3 + 2] = 2.f * v2 / 7.f - 1.f;
}

// ---------------- K4: trilinear grid sample (faithful to reference axis mapping) ----------------
__global__ void __launch_bounds__(256) k_sample(const float* __restrict__ x) {
    int idx = blockIdx.x * blockDim.x + threadIdx.x;  // NBG*CG*PJ = 65536
    if (idx >= NBG * CG * PJ) return;
    int j = idx & 127;
    int c = (idx >> 7) & 63;
    int bg = idx >> 13;
    int b = bg >> 2, g = bg & 3;
    const float* gr = g_grid + (bg * 128 + j) * 3;
    float n0 = gr[0], n1 = gr[1], n2 = gr[2];
    // reference: grid[...,0] -> x (W=16), grid[...,1] -> y (H=16), grid[...,2] -> z (D=4)
    float ix = ((n0 + 1.f) * 16.f - 1.f) * 0.5f;
    float iy = ((n1 + 1.f) * 16.f - 1.f) * 0.5f;
    float iz = ((n2 + 1.f) * 4.f - 1.f) * 0.5f;
    float x0f = floorf(ix), y0f = floorf(iy), z0f = floorf(iz);
    float tx = ix - x0f, ty = iy - y0f, tz = iz - z0f;
    const float* vol = x + (b * 256 + g * 64 + c) * 1024;
    float acc = 0.f;
#pragma unroll
    for (int dz = 0; dz < 2; dz++) {
#pragma unroll
        for (int dy = 0; dy < 2; dy++) {
#pragma unroll
            for (int dx = 0; dx < 2; dx++) {
                float xc = x0f + dx, yc = y0f + dy, zc = z0f + dz;
                float wgt = (dx ? tx : 1.f - tx) * (dy ? ty : 1.f - ty) * (dz ? tz : 1.f - tz);
                if (xc >= 0.f && xc < 16.f && yc >= 0.f && yc < 16.f && zc >= 0.f && zc < 4.f) {
                    int xi = (int)xc, yi = (int)yc, zi = (int)zc;
                    acc = fmaf(vol[(zi * 16 + yi) * 16 + xi], wgt, acc);
                }
            }
        }
    }
    g_kv[(bg * 64 + c) * 128 + j] = acc;
}

// ---------------- K5: k and v projections ----------------
__global__ void __launch_bounds__(128) k_kv(const float* __restrict__ wk,
                                            const float* __restrict__ wv) {
    __shared__ float sw[128 * 64];
    int bg = blockIdx.x;
    int g = bg & 3;
    int tid = threadIdx.x;  // j
    float kr[64];
#pragma unroll
    for (int i = 0; i < 64; i++) kr[i] = g_kv[(bg * 64 + i) * 128 + tid];
    for (int t = tid; t < 8192; t += 128) sw[t] = wk[g * 8192 + t];
    __syncthreads();
    for (int o = 0; o < 128; o++) {
        float a = 0.f;
#pragma unroll
        for (int i = 0; i < 64; i++) a = fmaf(kr[i], sw[o * 64 + i], a);
        g_k[(bg * 128 + o) * 128 + tid] = a;
    }
    __syncthreads();
    for (int t = tid; t < 8192; t += 128) sw[t] = wv[g * 8192 + t];
    __syncthreads();
    for (int o = 0; o < 128; o++) {
        float a = 0.f;
#pragma unroll
        for (int i = 0; i < 64; i++) a = fmaf(kr[i], sw[o * 64 + i], a);
        g_v[(bg * 128 + o) * 128 + tid] = a;
    }
}

// ---------------- K6: fused CPB-MLP + sim + softmax + attn@V ----------------
// smem layout (floats)
#define SK_OFF   0
#define SV_OFF   (128 * 129)
#define SW1_OFF  (2 * 128 * 129)
#define SW0_OFF  (SW1_OFF + 4096)
#define SB0_OFF  (SW0_OFF + 192)
#define SB1_OFF  (SB0_OFF + 64)
#define SW2_OFF  (SB1_OFF + 64)
#define SGK_OFF  (SW2_OFF + 128)
#define SQC_OFF  (SGK_OFF + 384)
#define SAT_OFF  (SQC_OFF + 256)
#define SRD_OFF  (SAT_OFF + 512)
#define SM6_FLOATS (SRD_OFF + 32)
#define SM6_BYTES  (SM6_FLOATS * 4)

__global__ void __launch_bounds__(256, 1) k_attn(
    const float* __restrict__ cw0, const float* __restrict__ cb0,
    const float* __restrict__ cw1, const float* __restrict__ cb1,
    const float* __restrict__ cw2, const float* __restrict__ cb2) {
    extern __shared__ float sm[];
    float* s_k   = sm + SK_OFF;
    float* s_v   = sm + SV_OFF;
    float* s_w1  = sm + SW1_OFF;
    float* s_w0  = sm + SW0_OFF;
    float* s_b0  = sm + SB0_OFF;
    float* s_b1  = sm + SB1_OFF;
    float* s_w2  = sm + SW2_OFF;
    float* s_gkv = sm + SGK_OFF;
    float* s_qc  = sm + SQC_OFF;   // [256]  (two halves)
    float* s_at  = sm + SAT_OFF;   // [2 half][2 head][128]
    float* s_rd  = sm + SRD_OFF;   // [32]

    int bid = blockIdx.x;
    int bg = bid >> 7;
    int itile = bid & 127;
    int b = bg >> 2, g = bg & 3;
    int tid = threadIdx.x;          // 256
    int hf = tid >> 7;              // which of 2 i-slices
    int j = tid & 127;
    int warp = tid >> 5;            // 0..7

    for (int t = tid; t < 4096; t += 256) s_w1[t] = cw1[t];
    if (tid < 192) s_w0[tid] = cw0[tid];
    if (tid < 64) { s_b0[tid] = cb0[tid]; s_b1[tid] = cb1[tid]; }
    if (tid >= 64 && tid < 192) s_w2[tid - 64] = cw2[tid - 64];
    for (int t = tid; t < 384; t += 256) s_gkv[t] = g_grid[bg * 384 + t];
    for (int t = tid; t < 128 * 128; t += 256) {
        int o = t >> 7, jj = t & 127;
        s_k[o * 129 + jj] = g_k[bg * 16384 + t];
        s_v[o * 129 + jj] = g_v[bg * 16384 + t];
    }
    float b2_0 = cb2[0], b2_1 = cb2[1];
    __syncthreads();

    float gk0 = s_gkv[j * 3 + 0], gk1 = s_gkv[j * 3 + 1], gk2 = s_gkv[j * 3 + 2];

    for (int it = 0; it < 4; it++) {
        int i = itile * 8 + it * 2 + hf;
        s_qc[tid] = g_q[(bg * 128 + j) * 1024 + i] * 0.125f;
        __syncthreads();

        // ---- CPB bias MLP for pair (i, j) ----
        int fi = i >> 8, hy = (i >> 4) & 15, wx = i & 15;
        float p0 = (2.f * (float)fi / 3.f - 1.f) - gk0;
        float p1 = (2.f * (float)hy / 15.f - 1.f) - gk1;
        float p2 = (2.f * (float)wx / 15.f - 1.f) - gk2;
        float s0 = copysignf(log1pf(fabsf(p0)), p0);
        float s1 = copysignf(log1pf(fabsf(p1)), p1);
        float s2 = copysignf(log1pf(fabsf(p2)), p2);

        unsigned long long acc[32];
#pragma unroll
        for (int k = 0; k < 32; k++) acc[k] = pk2(s_b1[2 * k], s_b1[2 * k + 1]);

#pragma unroll 4
        for (int k1 = 0; k1 < 64; k1++) {
            float hv = fmaf(s0, s_w0[k1],
                       fmaf(s1, s_w0[64 + k1],
                       fmaf(s2, s_w0[128 + k1], s_b0[k1])));
            hv = fmaxf(hv, 0.f);
            unsigned long long hp = pk2(hv, hv);
            const unsigned long long* wrow = (const unsigned long long*)(s_w1 + k1 * 64);
#pragma unroll
            for (int k = 0; k < 32; k++) acc[k] = ffma2(hp, wrow[k], acc[k]);
        }
        float bias0 = b2_0, bias1 = b2_1;
#pragma unroll
        for (int k = 0; k < 32; k++) {
            float t0, t1;
            upk2(acc[k], t0, t1);
            t0 = fmaxf(t0, 0.f);
            t1 = fmaxf(t1, 0.f);
            bias0 = fmaf(t0, s_w2[(2 * k) * 2 + 0], fmaf(t1, s_w2[(2 * k + 1) * 2 + 0], bias0));
            bias1 = fmaf(t0, s_w2[(2 * k) * 2 + 1], fmaf(t1, s_w2[(2 * k + 1) * 2 + 1], bias1));
        }

        // ---- sim for both heads of this group ----
        float sim0 = bias0, sim1 = bias1;
        const float* qc = s_qc + hf * 128;
#pragma unroll 8
        for (int d = 0; d < 64; d++) {
            sim0 = fmaf(qc[d], s_k[d * 129 + j], sim0);
            sim1 = fmaf(qc[64 + d], s_k[(64 + d) * 129 + j], sim1);
        }

        // ---- softmax across j (128 threads of this half) ----
        float m0 = sim0, m1 = sim1;
#pragma unroll
        for (int o = 16; o; o >>= 1) {
            m0 = fmaxf(m0, __shfl_xor_sync(0xffffffffu, m0, o));
            m1 = fmaxf(m1, __shfl_xor_sync(0xffffffffu, m1, o));
        }
        if ((tid & 31) == 0) { s_rd[warp] = m0; s_rd[8 + warp] = m1; }
        __syncthreads();
        int hb = hf * 4;
        m0 = fmaxf(fmaxf(s_rd[hb], s_rd[hb + 1]), fmaxf(s_rd[hb + 2], s_rd[hb + 3]));
        m1 = fmaxf(fmaxf(s_rd[8 + hb], s_rd[8 + hb + 1]), fmaxf(s_rd[8 + hb + 2], s_rd[8 + hb + 3]));
        float e0 = __expf(sim0 - m0);
        float e1 = __expf(sim1 - m1);
        float t0 = e0, t1 = e1;
#pragma unroll
        for (int o = 16; o; o >>= 1) {
            t0 += __shfl_xor_sync(0xffffffffu, t0, o);
            t1 += __shfl_xor_sync(0xffffffffu, t1, o);
        }
        if ((tid & 31) == 0) { s_rd[16 + warp] = t0; s_rd[24 + warp] = t1; }
        __syncthreads();
        float sum0 = s_rd[16 + hb] + s_rd[16 + hb + 1] + s_rd[16 + hb + 2] + s_rd[16 + hb + 3];
        float sum1 = s_rd[24 + hb] + s_rd[24 + hb + 1] + s_rd[24 + hb + 2] + s_rd[24 + hb + 3];
        s_at[hf * 256 + j] = e0 / sum0;
        s_at[hf * 256 + 128 + j] = e1 / sum1;
        __syncthreads();

        // ---- out[row] = sum_j attn[hpg][j] * v[row][j],  row = hpg*64+d = j-lane ----
        int row = j;  // 0..127 covers both heads of the group
        const float* vrow = s_v + row * 129;
        const float* arow = s_at + hf * 256 + (row >> 6) * 128;
        float oacc = 0.f;
#pragma unroll 16
        for (int jj = 0; jj < 128; jj++) oacc = fmaf(arow[jj], vrow[jj], oacc);
        g_att[(b * 512 + g * 128 + row) * 1024 + i] = oacc;
        __syncthreads();
    }
}

// ---------------- K7: final projection ----------------
__global__ void __launch_bounds__(256) k_proj(const float* __restrict__ wo,
                                              const float* __restrict__ bo,
                                              float* __restrict__ out) {
    __shared__ float s_wo[16 * 512];  // [c][u]
    int bid = blockIdx.x;
    int pt = bid & 3;
    int og = (bid >> 2) & 15;
    int b = bid >> 6;
    int tid = threadIdx.x;
    for (int t = tid; t < 16 * 512; t += 256) {
        int u = t & 15;
        int c = t >> 4;
        s_wo[c * 16 + u] = wo[(og * 16 + u) * 512 + c];
    }
    __syncthreads();
    int p = pt * 256 + tid;
    const float* arow = g_att + b * 512 * 1024 + p;
    float acc[16];
#pragma unroll
    for (int u = 0; u < 16; u++) acc[u] = 0.f;
    for (int c = 0; c < 512; c++) {
        float a = arow[c * 1024];
        const float4* w4 = (const float4*)(s_wo + c * 16);
#pragma unroll
        for (int q4 = 0; q4 < 4; q4++) {
            float4 wv = w4[q4];
            acc[q4 * 4 + 0] = fmaf(a, wv.x, acc[q4 * 4 + 0]);
            acc[q4 * 4 + 1] = fmaf(a, wv.y, acc[q4 * 4 + 1]);
            acc[q4 * 4 + 2] = fmaf(a, wv.z, acc[q4 * 4 + 2]);
            acc[q4 * 4 + 3] = fmaf(a, wv.w, acc[q4 * 4 + 3]);
        }
    }
#pragma unroll
    for (int u = 0; u < 16; u++)
        out[(b * 256 + og * 16 + u) * 1024 + p] = acc[u] + bo[og * 16 + u];
}

// ---------------- launch ----------------
extern "C" void kernel_launch(void* const* d_in, const int* in_sizes, int n_in,
                              void* d_out, int out_size) {
    const float* x   = (const float*)d_in[0];
    const float* wq  = (const float*)d_in[1];
    const float* wk  = (const float*)d_in[2];
    const float* wv  = (const float*)d_in[3];
    const float* dww = (const float*)d_in[4];
    const float* dwb = (const float*)d_in[5];
    const float* pw  = (const float*)d_in[6];
    const float* w0  = (const float*)d_in[7];
    const float* b0  = (const float*)d_in[8];
    const float* w1  = (const float*)d_in[9];
    const float* b1  = (const float*)d_in[10];
    const float* w2  = (const float*)d_in[11];
    const float* b2  = (const float*)d_in[12];
    const float* wo  = (const float*)d_in[13];
    const float* bo  = (const float*)d_in[14];
    float* out = (float*)d_out;

    cudaFuncSetAttribute(k_attn, cudaFuncAttributeMaxDynamicSharedMemorySize, SM6_BYTES);

    k_q<<<dim3(NBG, 8), 128>>>(x, wq);
    k_dw<<<(NBG * 128 * PJ + 255) / 256, 256>>>(dww, dwb);
    k_off<<<(NBG * PJ + 255) / 256, 256>>>(pw);
    k_sample<<<(NBG * CG * PJ + 255) / 256, 256>>>(x);
    k_kv<<<NBG, 128>>>(wk, wv);
    k_attn<<<NBG * 128, 256, SM6_BYTES>>>(w0, b0, w1, b1, w2, b2);
    k_proj<<<NB * 16 * 4, 256>>>(wo, bo, out);
}

// round 2
// speedup vs baseline: 1.1086x; 1.1086x over previous
#include <cuda_runtime.h>
#include <cuda_bf16.h>
#include <math.h>

// ---------------- problem constants ----------------
#define NB    2
#define NG    4
#define NBG   8          // NB*NG
#define PQ    1024       // 4*16*16
#define PJ    128        // 2*8*8
#define CG    64         // DIM/GROUPS

// ---------------- scratch ----------------
__device__ float g_q[NBG * 128 * PQ];     // [bg][o][p]
__device__ float g_dw[NBG * 128 * PJ];    // [bg][c][j]
__device__ float g_grid[NBG * PJ * 3];    // [bg][j][3]
__device__ float g_kv[NBG * CG * PJ];     // [bg][i][j]
__device__ float g_k[NBG * 128 * PJ];     // [bg][o][j]
__device__ float g_v[NBG * 128 * PJ];
__device__ float g_bias[NBG * PQ * 2 * PJ]; // [bg][i][hpg][j]
__device__ float g_att[NB * 512 * PQ];    // [b][c][p]

// ---------------- f32x2 helpers ----------------
typedef unsigned long long ull;
__device__ __forceinline__ ull pk2(float lo, float hi) {
    ull r; asm("mov.b64 %0, {%1, %2};" : "=l"(r) : "f"(lo), "f"(hi)); return r;
}
__device__ __forceinline__ void upk2(ull v, float& lo, float& hi) {
    asm("mov.b64 {%0, %1}, %2;" : "=f"(lo), "=f"(hi) : "l"(v));
}
__device__ __forceinline__ ull ffma2(ull a, ull b, ull c) {
    ull d; asm("fma.rn.f32x2 %0, %1, %2, %3;" : "=l"(d) : "l"(a), "l"(b), "l"(c)); return d;
}

// ---------------- K1: grouped 1x1 conv -> q ----------------
// grid (NBG, 8 ptiles, 4 ochunks), 128 threads (p)
__global__ void __launch_bounds__(128) k_q(const float* __restrict__ x,
                                           const float* __restrict__ wq) {
    __shared__ float swt[64][36];   // [i][o_local], padded
    int bg = blockIdx.x, pt = blockIdx.y, oc = blockIdx.z;
    int b = bg >> 2, g = bg & 3;
    int tid = threadIdx.x;
    for (int t = tid; t < 2048; t += 128) {
        int o = t >> 6, i = t & 63;
        swt[i][o] = wq[g * 8192 + (oc * 32 + o) * 64 + i];
    }
    __syncthreads();
    int p = pt * 128 + tid;
    float xr[64];
#pragma unroll
    for (int i = 0; i < 64; i++) xr[i] = x[(b * 256 + g * 64 + i) * 1024 + p];
    ull acc[16];
#pragma unroll
    for (int c = 0; c < 16; c++) acc[c] = 0ull;
#pragma unroll 8
    for (int i = 0; i < 64; i++) {
        ull xp = pk2(xr[i], xr[i]);
        const ulonglong2* wr = (const ulonglong2*)(&swt[i][0]);
#pragma unroll
        for (int m = 0; m < 8; m++) {
            ulonglong2 w = wr[m];
            acc[2 * m]     = ffma2(xp, w.x, acc[2 * m]);
            acc[2 * m + 1] = ffma2(xp, w.y, acc[2 * m + 1]);
        }
    }
#pragma unroll
    for (int c = 0; c < 16; c++) {
        float lo, hi; upk2(acc[c], lo, hi);
        int o = oc * 32 + 2 * c;
        g_q[(bg * 128 + o) * 1024 + p] = lo;
        g_q[(bg * 128 + o + 1) * 1024 + p] = hi;
    }
}

// ---------------- K2: depthwise strided conv + bias + exact GELU ----------------
__global__ void __launch_bounds__(256) k_dw(const float* __restrict__ w,
                                            const float* __restrict__ bias) {
    int idx = blockIdx.x * blockDim.x + threadIdx.x;
    if (idx >= NBG * 128 * PJ) return;
    int j = idx & 127;
    int c = (idx >> 7) & 127;
    int bg = idx >> 14;
    int zo = j >> 6, yo = (j >> 3) & 7, xo = j & 7;
    const float* qb = g_q + (bg * 128 + c) * 1024;
    const float* wc = w + c * 64;
    float acc = 0.f;
#pragma unroll
    for (int kz = 0; kz < 4; kz++) {
        int zi = zo * 2 - 1 + kz;
        if (zi < 0 || zi >= 4) continue;
#pragma unroll
        for (int ky = 0; ky < 4; ky++) {
            int yi = yo * 2 - 1 + ky;
            if (yi < 0 || yi >= 16) continue;
#pragma unroll
            for (int kx = 0; kx < 4; kx++) {
                int xi = xo * 2 - 1 + kx;
                if (xi < 0 || xi >= 16) continue;
                acc = fmaf(qb[(zi * 16 + yi) * 16 + xi], wc[(kz * 4 + ky) * 4 + kx], acc);
            }
        }
    }
    acc += bias[c];
    float ge = 0.5f * acc * (1.f + erff(acc * 0.70710678118654752f));
    g_dw[idx] = ge;
}

// ---------------- K3: pointwise -> tanh -> offsets -> normalized grid ----------------
__global__ void __launch_bounds__(256) k_off(const float* __restrict__ pw) {
    int idx = blockIdx.x * blockDim.x + threadIdx.x;
    if (idx >= NBG * PJ) return;
    int j = idx & 127;
    int bg = idx >> 7;
    float a0 = 0.f, a1 = 0.f, a2 = 0.f;
#pragma unroll 8
    for (int c = 0; c < 128; c++) {
        float v = g_dw[(bg * 128 + c) * 128 + j];
        a0 = fmaf(v, pw[c], a0);
        a1 = fmaf(v, pw[128 + c], a1);
        a2 = fmaf(v, pw[256 + c], a2);
    }
    float o0 = tanhf(a0) * 2.f, o1 = tanhf(a1) * 2.f, o2 = tanhf(a2) * 2.f;
    int fz = j >> 6, hy = (j >> 3) & 7, wx = j & 7;
    float v0 = (float)fz + o0, v1 = (float)hy + o1, v2 = (float)wx + o2;
    g_grid[idx * 3 + 0] = 2.f * v0 - 1.f;
    g_grid[idx * 3 + 1] = 2.f * v1 / 7.f - 1.f;
    g_grid[idx * 3 + 2] = 2.f * v2 / 7.f - 1.f;
}

// ---------------- K4: trilinear grid sample ----------------
__global__ void __launch_bounds__(256) k_sample(const float* __restrict__ x) {
    int idx = blockIdx.x * blockDim.x + threadIdx.x;
    if (idx >= NBG * CG * PJ) return;
    int j = idx & 127;
    int c = (idx >> 7) & 63;
    int bg = idx >> 13;
    int b = bg >> 2, g = bg & 3;
    const float* gr = g_grid + (bg * 128 + j) * 3;
    float n0 = gr[0], n1 = gr[1], n2 = gr[2];
    float ix = ((n0 + 1.f) * 16.f - 1.f) * 0.5f;
    float iy = ((n1 + 1.f) * 16.f - 1.f) * 0.5f;
    float iz = ((n2 + 1.f) * 4.f - 1.f) * 0.5f;
    float x0f = floorf(ix), y0f = floorf(iy), z0f = floorf(iz);
    float tx = ix - x0f, ty = iy - y0f, tz = iz - z0f;
    const float* vol = x + (b * 256 + g * 64 + c) * 1024;
    float acc = 0.f;
#pragma unroll
    for (int dz = 0; dz < 2; dz++)
#pragma unroll
        for (int dy = 0; dy < 2; dy++)
#pragma unroll
            for (int dx = 0; dx < 2; dx++) {
                float xc = x0f + dx, yc = y0f + dy, zc = z0f + dz;
                float wgt = (dx ? tx : 1.f - tx) * (dy ? ty : 1.f - ty) * (dz ? tz : 1.f - tz);
                if (xc >= 0.f && xc < 16.f && yc >= 0.f && yc < 16.f && zc >= 0.f && zc < 4.f) {
                    int xi = (int)xc, yi = (int)yc, zi = (int)zc;
                    acc = fmaf(vol[(zi * 16 + yi) * 16 + xi], wgt, acc);
                }
            }
    g_kv[(bg * 64 + c) * 128 + j] = acc;
}

// ---------------- K5: k and v projections ----------------
// grid (NBG, 4 ochunks, 2 sel), 128 threads (j)
__global__ void __launch_bounds__(128) k_kv(const float* __restrict__ wk,
                                            const float* __restrict__ wv) {
    __shared__ float swt[64][36];
    int bg = blockIdx.x, oc = blockIdx.y, sel = blockIdx.z;
    int g = bg & 3;
    int tid = threadIdx.x;
    const float* w = sel ? wv : wk;
    float* outp = sel ? g_v : g_k;
    for (int t = tid; t < 2048; t += 128) {
        int o = t >> 6, i = t & 63;
        swt[i][o] = w[g * 8192 + (oc * 32 + o) * 64 + i];
    }
    __syncthreads();
    float kr[64];
#pragma unroll
    for (int i = 0; i < 64; i++) kr[i] = g_kv[(bg * 64 + i) * 128 + tid];
    ull acc[16];
#pragma unroll
    for (int c = 0; c < 16; c++) acc[c] = 0ull;
#pragma unroll 8
    for (int i = 0; i < 64; i++) {
        ull xp = pk2(kr[i], kr[i]);
        const ulonglong2* wr = (const ulonglong2*)(&swt[i][0]);
#pragma unroll
        for (int m = 0; m < 8; m++) {
            ulonglong2 ww = wr[m];
            acc[2 * m]     = ffma2(xp, ww.x, acc[2 * m]);
            acc[2 * m + 1] = ffma2(xp, ww.y, acc[2 * m + 1]);
        }
    }
#pragma unroll
    for (int c = 0; c < 16; c++) {
        float lo, hi; upk2(acc[c], lo, hi);
        int o = oc * 32 + 2 * c;
        outp[(bg * 128 + o) * 128 + tid] = lo;
        outp[(bg * 128 + o + 1) * 128 + tid] = hi;
    }
}

// ---------------- K6a: CPB bias MLP (register-blocked GEMM) ----------------
// grid 4096: bid -> (bg, ipair). CTA handles 2 consecutive i's, all 128 j.
// 256 threads: pg = tid>>3 (0..31, 4 j's each), kg = tid&7 (8 k2's each).
// smem floats:
#define A_H    0                    // 64*128
#define A_W1   (A_H + 8192)         // 64*64
#define A_W0   (A_W1 + 4096)        // 192
#define A_B0   (A_W0 + 192)         // 64
#define A_B1   (A_B0 + 64)          // 64
#define A_W2   (A_B1 + 64)          // 128
#define A_S0   (A_W2 + 128)         // 128
#define A_S1   (A_S0 + 128)
#define A_S2   (A_S1 + 128)
#define A_FLOATS (A_S2 + 128)
#define A_BYTES  (A_FLOATS * 4)

__global__ void __launch_bounds__(256) k_bias(
    const float* __restrict__ cw0, const float* __restrict__ cb0,
    const float* __restrict__ cw1, const float* __restrict__ cb1,
    const float* __restrict__ cw2, const float* __restrict__ cb2) {
    extern __shared__ float sm[];
    float* s_H  = sm + A_H;
    float* s_w1 = sm + A_W1;
    float* s_w0 = sm + A_W0;
    float* s_b0 = sm + A_B0;
    float* s_b1 = sm + A_B1;
    float* s_w2 = sm + A_W2;
    float* s_s0 = sm + A_S0;
    float* s_s1 = sm + A_S1;
    float* s_s2 = sm + A_S2;

    int bid = blockIdx.x;
    int bg = bid >> 9;              // 0..7
    int ibase = (bid & 511) * 2;    // 0..1022 step 2
    int tid = threadIdx.x;
    int pg = tid >> 3, kg = tid & 7;

    for (int t = tid; t < 4096; t += 256) s_w1[t] = cw1[t];
    if (tid < 192) s_w0[tid] = cw0[tid];
    if (tid < 64) { s_b0[tid] = cb0[tid]; s_b1[tid] = cb1[tid]; }
    if (tid >= 64 && tid < 192) s_w2[tid - 64] = cw2[tid - 64];
    float b2_0 = cb2[0], b2_1 = cb2[1];

    // preload grid coords for this thread's role (tid<128 computes s)
    float gk0 = 0.f, gk1 = 0.f, gk2 = 0.f;
    if (tid < 128) {
        gk0 = g_grid[(bg * 128 + tid) * 3 + 0];
        gk1 = g_grid[(bg * 128 + tid) * 3 + 1];
        gk2 = g_grid[(bg * 128 + tid) * 3 + 2];
    }

    // b1 init values for this thread's k2 chunk
    ull binit[4];
    {
        // ensure s_b1 loaded
        __syncthreads();
#pragma unroll
        for (int c = 0; c < 4; c++)
            binit[c] = pk2(s_b1[kg * 8 + 2 * c], s_b1[kg * 8 + 2 * c + 1]);
    }

    for (int isub = 0; isub < 2; isub++) {
        int i = ibase + isub;
        // ---- s vectors ----
        if (tid < 128) {
            int fi = i >> 8, hy = (i >> 4) & 15, wx = i & 15;
            float p0 = (2.f * (float)fi / 3.f - 1.f) - gk0;
            float p1 = (2.f * (float)hy / 15.f - 1.f) - gk1;
            float p2 = (2.f * (float)wx / 15.f - 1.f) - gk2;
            s_s0[tid] = copysignf(log1pf(fabsf(p0)), p0);
            s_s1[tid] = copysignf(log1pf(fabsf(p1)), p1);
            s_s2[tid] = copysignf(log1pf(fabsf(p2)), p2);
        }
        __syncthreads();
        // ---- H = relu(W0 s + b0) : [64 k1][128 j] ----
        {
            int j = tid & 127;
            int kb = (tid >> 7) * 32;
            float v0 = s_s0[j], v1 = s_s1[j], v2 = s_s2[j];
#pragma unroll 8
            for (int kk = 0; kk < 32; kk++) {
                int k1 = kb + kk;
                float h = fmaf(v0, s_w0[k1],
                          fmaf(v1, s_w0[64 + k1],
                          fmaf(v2, s_w0[128 + k1], s_b0[k1])));
                s_H[k1 * 128 + j] = fmaxf(h, 0.f);
            }
        }
        __syncthreads();
        // ---- layer 1 GEMM: 4 pairs x 8 k2 per thread ----
        ull acc[16];
#pragma unroll
        for (int p = 0; p < 4; p++)
#pragma unroll
            for (int c = 0; c < 4; c++) acc[p * 4 + c] = binit[c];

#pragma unroll 8
        for (int k1 = 0; k1 < 64; k1++) {
            float4 h4 = *(const float4*)(s_H + k1 * 128 + pg * 4);
            const ulonglong2* wr = (const ulonglong2*)(s_w1 + k1 * 64 + kg * 8);
            ulonglong2 wa = wr[0], wb = wr[1];
            ull hp0 = pk2(h4.x, h4.x), hp1 = pk2(h4.y, h4.y);
            ull hp2 = pk2(h4.z, h4.z), hp3 = pk2(h4.w, h4.w);
            acc[0]  = ffma2(hp0, wa.x, acc[0]);
            acc[1]  = ffma2(hp0, wa.y, acc[1]);
            acc[2]  = ffma2(hp0, wb.x, acc[2]);
            acc[3]  = ffma2(hp0, wb.y, acc[3]);
            acc[4]  = ffma2(hp1, wa.x, acc[4]);
            acc[5]  = ffma2(hp1, wa.y, acc[5]);
            acc[6]  = ffma2(hp1, wb.x, acc[6]);
            acc[7]  = ffma2(hp1, wb.y, acc[7]);
            acc[8]  = ffma2(hp2, wa.x, acc[8]);
            acc[9]  = ffma2(hp2, wa.y, acc[9]);
            acc[10] = ffma2(hp2, wb.x, acc[10]);
            acc[11] = ffma2(hp2, wb.y, acc[11]);
            acc[12] = ffma2(hp3, wa.x, acc[12]);
            acc[13] = ffma2(hp3, wa.y, acc[13]);
            acc[14] = ffma2(hp3, wb.x, acc[14]);
            acc[15] = ffma2(hp3, wb.y, acc[15]);
        }
        // ---- layer 2 + reduce over kg ----
#pragma unroll
        for (int p = 0; p < 4; p++) {
            float bias0 = 0.f, bias1 = 0.f;
#pragma unroll
            for (int c = 0; c < 4; c++) {
                float t0, t1; upk2(acc[p * 4 + c], t0, t1);
                t0 = fmaxf(t0, 0.f); t1 = fmaxf(t1, 0.f);
                int k2a = kg * 8 + 2 * c, k2b = k2a + 1;
                bias0 = fmaf(t0, s_w2[k2a * 2 + 0], fmaf(t1, s_w2[k2b * 2 + 0], bias0));
                bias1 = fmaf(t0, s_w2[k2a * 2 + 1], fmaf(t1, s_w2[k2b * 2 + 1], bias1));
            }
#pragma unroll
            for (int off = 4; off; off >>= 1) {
                bias0 += __shfl_down_sync(0xffffffffu, bias0, off, 8);
                bias1 += __shfl_down_sync(0xffffffffu, bias1, off, 8);
            }
            if (kg == 0) {
                int j = pg * 4 + p;
                g_bias[((bg * 1024 + i) * 2 + 0) * 128 + j] = bias0 + b2_0;
                g_bias[((bg * 1024 + i) * 2 + 1) * 128 + j] = bias1 + b2_1;
            }
        }
        __syncthreads();  // protect s_s / s_H before next isub
    }
}

// ---------------- K6b: sim + bias + softmax + attn@V ----------------
#define B_KT   0                         // 128*132 (K transposed, [j][d])
#define B_V    (B_KT + 128 * 132)        // 128*132 ([o][j])
#define B_QC   (B_V + 128 * 132)         // 256
#define B_AT   (B_QC + 256)              // 512
#define B_RD   (B_AT + 512)              // 32
#define B_FLOATS (B_RD + 32)
#define B_BYTES  (B_FLOATS * 4)

__global__ void __launch_bounds__(256, 1) k_attn(int dummy) {
    extern __shared__ float sm[];
    float* s_kt = sm + B_KT;
    float* s_v  = sm + B_V;
    float* s_qc = sm + B_QC;
    float* s_at = sm + B_AT;
    float* s_rd = sm + B_RD;

    int bid = blockIdx.x;
    int bg = bid >> 6;
    int itile = bid & 63;
    int b = bg >> 2, g = bg & 3;
    int tid = threadIdx.x;
    int hf = tid >> 7;
    int j = tid & 127;
    int warp = tid >> 5;

    for (int t = tid; t < 16384; t += 256) {
        int d = t >> 7, jj = t & 127;
        s_kt[jj * 132 + d] = g_k[bg * 16384 + t];
        s_v[d * 132 + jj]  = g_v[bg * 16384 + t];
    }
    __syncthreads();

    const float4* ktp = (const float4*)(s_kt + j * 132);

    for (int it = 0; it < 8; it++) {
        int i = itile * 16 + it * 2 + hf;
        s_qc[tid] = g_q[(bg * 128 + j) * 1024 + i] * 0.125f;
        float bias0 = g_bias[((bg * 1024 + i) * 2 + 0) * 128 + j];
        float bias1 = g_bias[((bg * 1024 + i) * 2 + 1) * 128 + j];
        __syncthreads();

        const float4* qcp = (const float4*)(s_qc + hf * 128);
        float sim0 = bias0, sim1 = bias1;
#pragma unroll
        for (int d4 = 0; d4 < 16; d4++) {
            float4 kq = ktp[d4], qq = qcp[d4];
            sim0 = fmaf(qq.x, kq.x, sim0);
            sim0 = fmaf(qq.y, kq.y, sim0);
            sim0 = fmaf(qq.z, kq.z, sim0);
            sim0 = fmaf(qq.w, kq.w, sim0);
        }
#pragma unroll
        for (int d4 = 16; d4 < 32; d4++) {
            float4 kq = ktp[d4], qq = qcp[d4];
            sim1 = fmaf(qq.x, kq.x, sim1);
            sim1 = fmaf(qq.y, kq.y, sim1);
            sim1 = fmaf(qq.z, kq.z, sim1);
            sim1 = fmaf(qq.w, kq.w, sim1);
        }

        // softmax over j (128 threads per half)
        float m0 = sim0, m1 = sim1;
#pragma unroll
        for (int o = 16; o; o >>= 1) {
            m0 = fmaxf(m0, __shfl_xor_sync(0xffffffffu, m0, o));
            m1 = fmaxf(m1, __shfl_xor_sync(0xffffffffu, m1, o));
        }
        if ((tid & 31) == 0) { s_rd[warp] = m0; s_rd[8 + warp] = m1; }
        __syncthreads();
        int hb = hf * 4;
        m0 = fmaxf(fmaxf(s_rd[hb], s_rd[hb + 1]), fmaxf(s_rd[hb + 2], s_rd[hb + 3]));
        m1 = fmaxf(fmaxf(s_rd[8 + hb], s_rd[8 + hb + 1]), fmaxf(s_rd[8 + hb + 2], s_rd[8 + hb + 3]));
        float e0 = __expf(sim0 - m0);
        float e1 = __expf(sim1 - m1);
        float t0 = e0, t1 = e1;
#pragma unroll
        for (int o = 16; o; o >>= 1) {
            t0 += __shfl_xor_sync(0xffffffffu, t0, o);
            t1 += __shfl_xor_sync(0xffffffffu, t1, o);
        }
        if ((tid & 31) == 0) { s_rd[16 + warp] = t0; s_rd[24 + warp] = t1; }
        __syncthreads();
        float sum0 = s_rd[16 + hb] + s_rd[16 + hb + 1] + s_rd[16 + hb + 2] + s_rd[16 + hb + 3];
        float sum1 = s_rd[24 + hb] + s_rd[24 + hb + 1] + s_rd[24 + hb + 2] + s_rd[24 + hb + 3];
        s_at[hf * 256 + j] = e0 / sum0;
        s_at[hf * 256 + 128 + j] = e1 / sum1;
        __syncthreads();

        // out[row] = sum_j attn[hpg][jj] * v[row][jj]
        int row = j;
        const float4* vp = (const float4*)(s_v + row * 132);
        const float4* ap = (const float4*)(s_at + hf * 256 + (row >> 6) * 128);
        float oacc = 0.f;
#pragma unroll
        for (int j4 = 0; j4 < 32; j4++) {
            float4 av = ap[j4], vv = vp[j4];
            oacc = fmaf(av.x, vv.x, oacc);
            oacc = fmaf(av.y, vv.y, oacc);
            oacc = fmaf(av.z, vv.z, oacc);
            oacc = fmaf(av.w, vv.w, oacc);
        }
        g_att[(b * 512 + g * 128 + row) * 1024 + i] = oacc;
        __syncthreads();
    }
}

// ---------------- K7: final projection ----------------
__global__ void __launch_bounds__(256) k_proj(const float* __restrict__ wo,
                                              const float* __restrict__ bo,
                                              float* __restrict__ out) {
    __shared__ float s_wo[16 * 512];  // [c][u]
    int bid = blockIdx.x;
    int pt = bid & 3;
    int og = (bid >> 2) & 15;
    int b = bid >> 6;
    int tid = threadIdx.x;
    for (int t = tid; t < 16 * 512; t += 256) {
        int u = t & 15;
        int c = t >> 4;
        s_wo[c * 16 + u] = wo[(og * 16 + u) * 512 + c];
    }
    __syncthreads();
    int p = pt * 256 + tid;
    const float* arow = g_att + b * 512 * 1024 + p;
    ull acc[8];
#pragma unroll
    for (int m = 0; m < 8; m++) acc[m] = 0ull;
#pragma unroll 4
    for (int c = 0; c < 512; c++) {
        float a = arow[c * 1024];
        ull ap = pk2(a, a);
        const ulonglong2* wr = (const ulonglong2*)(s_wo + c * 16);
#pragma unroll
        for (int m = 0; m < 4; m++) {
            ulonglong2 wv2 = wr[m];
            acc[2 * m]     = ffma2(ap, wv2.x, acc[2 * m]);
            acc[2 * m + 1] = ffma2(ap, wv2.y, acc[2 * m + 1]);
        }
    }
#pragma unroll
    for (int m = 0; m < 8; m++) {
        float lo, hi; upk2(acc[m], lo, hi);
        int u = 2 * m;
        out[(b * 256 + og * 16 + u) * 1024 + p] = lo + bo[og * 16 + u];
        out[(b * 256 + og * 16 + u + 1) * 1024 + p] = hi + bo[og * 16 + u + 1];
    }
}

// ---------------- launch ----------------
extern "C" void kernel_launch(void* const* d_in, const int* in_sizes, int n_in,
                              void* d_out, int out_size) {
    const float* x   = (const float*)d_in[0];
    const float* wq  = (const float*)d_in[1];
    const float* wk  = (const float*)d_in[2];
    const float* wv  = (const float*)d_in[3];
    const float* dww = (const float*)d_in[4];
    const float* dwb = (const float*)d_in[5];
    const float* pw  = (const float*)d_in[6];
    const float* w0  = (const float*)d_in[7];
    const float* b0  = (const float*)d_in[8];
    const float* w1  = (const float*)d_in[9];
    const float* b1  = (const float*)d_in[10];
    const float* w2  = (const float*)d_in[11];
    const float* b2  = (const float*)d_in[12];
    const float* wo  = (const float*)d_in[13];
    const float* bo  = (const float*)d_in[14];
    float* out = (float*)d_out;

    static int inited = 0;
    if (!inited) {
        cudaFuncSetAttribute(k_bias, cudaFuncAttributeMaxDynamicSharedMemorySize, A_BYTES);
        cudaFuncSetAttribute(k_attn, cudaFuncAttributeMaxDynamicSharedMemorySize, B_BYTES);
        inited = 1;
    }

    k_q<<<dim3(NBG, 8, 4), 128>>>(x, wq);
    k_dw<<<(NBG * 128 * PJ + 255) / 256, 256>>>(dww, dwb);
    k_off<<<(NBG * PJ + 255) / 256, 256>>>(pw);
    k_sample<<<(NBG * CG * PJ + 255) / 256, 256>>>(x);
    k_kv<<<dim3(NBG, 4, 2), 128>>>(wk, wv);
    k_bias<<<NBG * 512, 256, A_BYTES>>>(w0, b0, w1, b1, w2, b2);
    k_attn<<<NBG * 64, 256, B_BYTES>>>(0);
    k_proj<<<NB * 16 * 4, 256>>>(wo, bo, out);
}

// round 5
// speedup vs baseline: 2.1365x; 1.9271x over previous
#include <cuda_runtime.h>
#include <cuda_bf16.h>
#include <math.h>
#include <stdint.h>

// ---------------- problem constants ----------------
#define NB    2
#define NG    4
#define NBG   8          // NB*NG
#define PQ    1024       // 4*16*16
#define PJ    128        // 2*8*8
#define CG    64         // DIM/GROUPS

// ---------------- scratch ----------------
__device__ float g_q[NBG * 128 * PQ];     // [bg][o][p]
__device__ float g_dw[NBG * 128 * PJ];    // [bg][c][j]
__device__ float g_grid[NBG * PJ * 3];    // [bg][j][3]
__device__ float g_kv[NBG * CG * PJ];     // [bg][i][j]
__device__ float g_k[NBG * 128 * PJ];     // [bg][o][j]
__device__ float g_v[NBG * 128 * PJ];
__device__ float g_bias[NBG * PQ * 2 * PJ]; // [bg][i][hpg][j]
__device__ float g_att[NB * 512 * PQ];    // [b][c][p]

// ---------------- f32x2 helpers (used where cheap) ----------------
typedef unsigned long long ull;
__device__ __forceinline__ ull pk2(float lo, float hi) {
    ull r; asm("mov.b64 %0, {%1, %2};" : "=l"(r) : "f"(lo), "f"(hi)); return r;
}
__device__ __forceinline__ void upk2(ull v, float& lo, float& hi) {
    asm("mov.b64 {%0, %1}, %2;" : "=f"(lo), "=f"(hi) : "l"(v));
}
__device__ __forceinline__ ull ffma2(ull a, ull b, ull c) {
    ull d; asm("fma.rn.f32x2 %0, %1, %2, %3;" : "=l"(d) : "l"(a), "l"(b), "l"(c)); return d;
}

// pack two fp32 -> bf16x2 (lo = first arg)
__device__ __forceinline__ uint32_t pkbf(float lo, float hi) {
    uint32_t r; asm("cvt.rn.bf16x2.f32 %0, %1, %2;" : "=r"(r) : "f"(hi), "f"(lo)); return r;
}
__device__ __forceinline__ uint32_t smaddr(const void* p) {
    uint32_t a;
    asm("{ .reg .u64 t; cvta.to.shared.u64 t, %1; cvt.u32.u64 %0, t; }" : "=r"(a) : "l"(p));
    return a;
}

// ---------------- K1: grouped 1x1 conv -> q ----------------
__global__ void __launch_bounds__(128) k_q(const float* __restrict__ x,
                                           const float* __restrict__ wq) {
    __shared__ float swt[64][36];
    int bg = blockIdx.x, pt = blockIdx.y, oc = blockIdx.z;
    int b = bg >> 2, g = bg & 3;
    int tid = threadIdx.x;
    for (int t = tid; t < 2048; t += 128) {
        int o = t >> 6, i = t & 63;
        swt[i][o] = wq[g * 8192 + (oc * 32 + o) * 64 + i];
    }
    __syncthreads();
    int p = pt * 128 + tid;
    float xr[64];
#pragma unroll
    for (int i = 0; i < 64; i++) xr[i] = x[(b * 256 + g * 64 + i) * 1024 + p];
    ull acc[16];
#pragma unroll
    for (int c = 0; c < 16; c++) acc[c] = 0ull;
#pragma unroll 8
    for (int i = 0; i < 64; i++) {
        ull xp = pk2(xr[i], xr[i]);
        const ulonglong2* wr = (const ulonglong2*)(&swt[i][0]);
#pragma unroll
        for (int m = 0; m < 8; m++) {
            ulonglong2 w = wr[m];
            acc[2 * m]     = ffma2(xp, w.x, acc[2 * m]);
            acc[2 * m + 1] = ffma2(xp, w.y, acc[2 * m + 1]);
        }
    }
#pragma unroll
    for (int c = 0; c < 16; c++) {
        float lo, hi; upk2(acc[c], lo, hi);
        int o = oc * 32 + 2 * c;
        g_q[(bg * 128 + o) * 1024 + p] = lo;
        g_q[(bg * 128 + o + 1) * 1024 + p] = hi;
    }
}

// ---------------- K2: depthwise strided conv + bias + exact GELU ----------------
__global__ void __launch_bounds__(256) k_dw(const float* __restrict__ w,
                                            const float* __restrict__ bias) {
    int idx = blockIdx.x * blockDim.x + threadIdx.x;
    if (idx >= NBG * 128 * PJ) return;
    int j = idx & 127;
    int c = (idx >> 7) & 127;
    int bg = idx >> 14;
    int zo = j >> 6, yo = (j >> 3) & 7, xo = j & 7;
    const float* qb = g_q + (bg * 128 + c) * 1024;
    const float* wc = w + c * 64;
    float acc = 0.f;
#pragma unroll
    for (int kz = 0; kz < 4; kz++) {
        int zi = zo * 2 - 1 + kz;
        if (zi < 0 || zi >= 4) continue;
#pragma unroll
        for (int ky = 0; ky < 4; ky++) {
            int yi = yo * 2 - 1 + ky;
            if (yi < 0 || yi >= 16) continue;
#pragma unroll
            for (int kx = 0; kx < 4; kx++) {
                int xi = xo * 2 - 1 + kx;
                if (xi < 0 || xi >= 16) continue;
                acc = fmaf(qb[(zi * 16 + yi) * 16 + xi], wc[(kz * 4 + ky) * 4 + kx], acc);
            }
        }
    }
    acc += bias[c];
    float ge = 0.5f * acc * (1.f + erff(acc * 0.70710678118654752f));
    g_dw[idx] = ge;
}

// ---------------- K3: pointwise -> tanh -> offsets -> normalized grid ----------------
__global__ void __launch_bounds__(256) k_off(const float* __restrict__ pw) {
    int idx = blockIdx.x * blockDim.x + threadIdx.x;
    if (idx >= NBG * PJ) return;
    int j = idx & 127;
    int bg = idx >> 7;
    float a0 = 0.f, a1 = 0.f, a2 = 0.f;
#pragma unroll 8
    for (int c = 0; c < 128; c++) {
        float v = g_dw[(bg * 128 + c) * 128 + j];
        a0 = fmaf(v, pw[c], a0);
        a1 = fmaf(v, pw[128 + c], a1);
        a2 = fmaf(v, pw[256 + c], a2);
    }
    float o0 = tanhf(a0) * 2.f, o1 = tanhf(a1) * 2.f, o2 = tanhf(a2) * 2.f;
    int fz = j >> 6, hy = (j >> 3) & 7, wx = j & 7;
    float v0 = (float)fz + o0, v1 = (float)hy + o1, v2 = (float)wx + o2;
    g_grid[idx * 3 + 0] = 2.f * v0 - 1.f;
    g_grid[idx * 3 + 1] = 2.f * v1 / 7.f - 1.f;
    g_grid[idx * 3 + 2] = 2.f * v2 / 7.f - 1.f;
}

// ---------------- K4: trilinear grid sample ----------------
__global__ void __launch_bounds__(256) k_sample(const float* __restrict__ x) {
    int idx = blockIdx.x * blockDim.x + threadIdx.x;
    if (idx >= NBG * CG * PJ) return;
    int j = idx & 127;
    int c = (idx >> 7) & 63;
    int bg = idx >> 13;
    int b = bg >> 2, g = bg & 3;
    const float* gr = g_grid + (bg * 128 + j) * 3;
    float n0 = gr[0], n1 = gr[1], n2 = gr[2];
    float ix = ((n0 + 1.f) * 16.f - 1.f) * 0.5f;
    float iy = ((n1 + 1.f) * 16.f - 1.f) * 0.5f;
    float iz = ((n2 + 1.f) * 4.f - 1.f) * 0.5f;
    float x0f = floorf(ix), y0f = floorf(iy), z0f = floorf(iz);
    float tx = ix - x0f, ty = iy - y0f, tz = iz - z0f;
    const float* vol = x + (b * 256 + g * 64 + c) * 1024;
    float acc = 0.f;
#pragma unroll
    for (int dz = 0; dz < 2; dz++)
#pragma unroll
        for (int dy = 0; dy < 2; dy++)
#pragma unroll
            for (int dx = 0; dx < 2; dx++) {
                float xc = x0f + dx, yc = y0f + dy, zc = z0f + dz;
                float wgt = (dx ? tx : 1.f - tx) * (dy ? ty : 1.f - ty) * (dz ? tz : 1.f - tz);
                if (xc >= 0.f && xc < 16.f && yc >= 0.f && yc < 16.f && zc >= 0.f && zc < 4.f) {
                    int xi = (int)xc, yi = (int)yc, zi = (int)zc;
                    acc = fmaf(vol[(zi * 16 + yi) * 16 + xi], wgt, acc);
                }
            }
    g_kv[(bg * 64 + c) * 128 + j] = acc;
}

// ---------------- K5: k and v projections ----------------
__global__ void __launch_bounds__(128) k_kv(const float* __restrict__ wk,
                                            const float* __restrict__ wv) {
    __shared__ float swt[64][36];
    int bg = blockIdx.x, oc = blockIdx.y, sel = blockIdx.z;
    int g = bg & 3;
    int tid = threadIdx.x;
    const float* w = sel ? wv : wk;
    float* outp = sel ? g_v : g_k;
    for (int t = tid; t < 2048; t += 128) {
        int o = t >> 6, i = t & 63;
        swt[i][o] = w[g * 8192 + (oc * 32 + o) * 64 + i];
    }
    __syncthreads();
    float kr[64];
#pragma unroll
    for (int i = 0; i < 64; i++) kr[i] = g_kv[(bg * 64 + i) * 128 + tid];
    ull acc[16];
#pragma unroll
    for (int c = 0; c < 16; c++) acc[c] = 0ull;
#pragma unroll 8
    for (int i = 0; i < 64; i++) {
        ull xp = pk2(kr[i], kr[i]);
        const ulonglong2* wr = (const ulonglong2*)(&swt[i][0]);
#pragma unroll
        for (int m = 0; m < 8; m++) {
            ulonglong2 ww = wr[m];
            acc[2 * m]     = ffma2(xp, ww.x, acc[2 * m]);
            acc[2 * m + 1] = ffma2(xp, ww.y, acc[2 * m + 1]);
        }
    }
#pragma unroll
    for (int c = 0; c < 16; c++) {
        float lo, hi; upk2(acc[c], lo, hi);
        int o = oc * 32 + 2 * c;
        outp[(bg * 128 + o) * 128 + tid] = lo;
        outp[(bg * 128 + o + 1) * 128 + tid] = hi;
    }
}

// ---------------- K6a: CPB bias MLP with bf16 HMMA (mma.sync m16n8k16) ----------------
// CTA: 128 threads (4 warps), 8 i's.  Grid = NBG*128.
// Per i: build H[128j x 64k1] bf16 (swizzled smem), each warp does 2 j-tiles of 16:
// C[16x64] = H-tile @ W1 (+b1), then relu(C)@W2 epilogue with quad reduce.
__global__ void __launch_bounds__(128) k_bias_mma(
    const float* __restrict__ cw0, const float* __restrict__ cb0,
    const float* __restrict__ cw1, const float* __restrict__ cb1,
    const float* __restrict__ cw2, const float* __restrict__ cb2) {
    __shared__ __align__(16) char s_Hb[16384];        // H: 128 rows x 128 bytes, swizzled
    __shared__ __align__(16) float s_w0[192];
    __shared__ __align__(16) float s_b0[64];
    __shared__ __align__(16) float s_w2[128];

    int bid = blockIdx.x;
    int bg = bid >> 7;
    int ibase = (bid & 127) * 8;
    int tid = threadIdx.x;
    int lane = tid & 31;
    int warp = tid >> 5;

    if (tid < 128) s_w0[tid] = cw0[tid];
    if (tid < 64) {
        s_w0[128 + tid] = cw0[128 + tid];
        s_b0[tid] = cb0[tid];
    }
    if (tid < 128) s_w2[tid] = cw2[tid];
    float b2_0 = cb2[0], b2_1 = cb2[1];

    // W1 fragments in registers (invariant): bf[ks][nt][0..1]
    int bk = (lane & 3) * 2;     // k-base within fragment
    int bn = lane >> 2;          // n within 8-tile
    uint32_t bf[4][8][2];
#pragma unroll
    for (int ks = 0; ks < 4; ks++)
#pragma unroll
        for (int nt = 0; nt < 8; nt++) {
            int n = nt * 8 + bn;
            int k0 = ks * 16 + bk;
            bf[ks][nt][0] = pkbf(cw1[k0 * 64 + n],       cw1[(k0 + 1) * 64 + n]);
            bf[ks][nt][1] = pkbf(cw1[(k0 + 8) * 64 + n], cw1[(k0 + 9) * 64 + n]);
        }
    // layer-1 bias (cols = nt*8 + bk, bk+1)
    float bv0[8], bv1[8];
#pragma unroll
    for (int nt = 0; nt < 8; nt++) {
        bv0[nt] = cb1[nt * 8 + bk];
        bv1[nt] = cb1[nt * 8 + bk + 1];
    }

    // grid coords for j = tid (128 threads == 128 j)
    float gk0 = g_grid[(bg * 128 + tid) * 3 + 0];
    float gk1 = g_grid[(bg * 128 + tid) * 3 + 1];
    float gk2 = g_grid[(bg * 128 + tid) * 3 + 2];

    uint32_t hbase = smaddr(s_Hb);
    __syncthreads();

    for (int ii = 0; ii < 8; ii++) {
        int i = ibase + ii;
        // ---- s vector for this j ----
        int fi = i >> 8, hy = (i >> 4) & 15, wx = i & 15;
        float p0 = (2.f * (float)fi / 3.f - 1.f) - gk0;
        float p1 = (2.f * (float)hy / 15.f - 1.f) - gk1;
        float p2 = (2.f * (float)wx / 15.f - 1.f) - gk2;
        float s0 = copysignf(log1pf(fabsf(p0)), p0);
        float s1 = copysignf(log1pf(fabsf(p1)), p1);
        float s2 = copysignf(log1pf(fabsf(p2)), p2);

        // ---- H row j=tid: 64 k's, 8 per iter, STS.128 swizzled ----
        {
            int rowoff = tid * 128;
            int swz = (tid & 7) << 4;
#pragma unroll
            for (int m = 0; m < 8; m++) {
                int k = m * 8;
                float4 wa0 = *(const float4*)(s_w0 + k);
                float4 wa1 = *(const float4*)(s_w0 + k + 4);
                float4 wb0 = *(const float4*)(s_w0 + 64 + k);
                float4 wb1 = *(const float4*)(s_w0 + 64 + k + 4);
                float4 wc0 = *(const float4*)(s_w0 + 128 + k);
                float4 wc1 = *(const float4*)(s_w0 + 128 + k + 4);
                float4 bb0 = *(const float4*)(s_b0 + k);
                float4 bb1 = *(const float4*)(s_b0 + k + 4);
                float h0 = fmaxf(fmaf(s0, wa0.x, fmaf(s1, wb0.x, fmaf(s2, wc0.x, bb0.x))), 0.f);
                float h1 = fmaxf(fmaf(s0, wa0.y, fmaf(s1, wb0.y, fmaf(s2, wc0.y, bb0.y))), 0.f);
                float h2 = fmaxf(fmaf(s0, wa0.z, fmaf(s1, wb0.z, fmaf(s2, wc0.z, bb0.z))), 0.f);
                float h3 = fmaxf(fmaf(s0, wa0.w, fmaf(s1, wb0.w, fmaf(s2, wc0.w, bb0.w))), 0.f);
                float h4 = fmaxf(fmaf(s0, wa1.x, fmaf(s1, wb1.x, fmaf(s2, wc1.x, bb1.x))), 0.f);
                float h5 = fmaxf(fmaf(s0, wa1.y, fmaf(s1, wb1.y, fmaf(s2, wc1.y, bb1.y))), 0.f);
                float h6 = fmaxf(fmaf(s0, wa1.z, fmaf(s1, wb1.z, fmaf(s2, wc1.z, bb1.z))), 0.f);
                float h7 = fmaxf(fmaf(s0, wa1.w, fmaf(s1, wb1.w, fmaf(s2, wc1.w, bb1.w))), 0.f);
                uint4 st;
                st.x = pkbf(h0, h1); st.y = pkbf(h2, h3);
                st.z = pkbf(h4, h5); st.w = pkbf(h6, h7);
                *(uint4*)(s_Hb + rowoff + ((m * 16) ^ swz)) = st;
            }
        }
        __syncthreads();

        // ---- 2 j-tiles per warp ----
#pragma unroll
        for (int jt2 = 0; jt2 < 2; jt2++) {
            int jt = warp + jt2 * 4;
            int j0 = jt * 16;
            float c[8][4];
#pragma unroll
            for (int nt = 0; nt < 8; nt++) {
                c[nt][0] = bv0[nt]; c[nt][1] = bv1[nt];
                c[nt][2] = bv0[nt]; c[nt][3] = bv1[nt];
            }
#pragma unroll
            for (int ks = 0; ks < 4; ks++) {
                int row = j0 + (lane & 15);
                int colb = ks * 32 + ((lane & 16) ? 16 : 0);
                uint32_t addr = hbase + row * 128 + (colb ^ ((row & 7) << 4));
                uint32_t a0, a1, a2, a3;
                asm volatile("ldmatrix.sync.aligned.m8n8.x4.shared.b16 {%0,%1,%2,%3}, [%4];"
                             : "=r"(a0), "=r"(a1), "=r"(a2), "=r"(a3) : "r"(addr));
#pragma unroll
                for (int nt = 0; nt < 8; nt++) {
                    asm volatile("mma.sync.aligned.m16n8k16.row.col.f32.bf16.bf16.f32 "
                                 "{%0,%1,%2,%3}, {%4,%5,%6,%7}, {%8,%9}, {%0,%1,%2,%3};"
                                 : "+f"(c[nt][0]), "+f"(c[nt][1]), "+f"(c[nt][2]), "+f"(c[nt][3])
                                 : "r"(a0), "r"(a1), "r"(a2), "r"(a3),
                                   "r"(bf[ks][nt][0]), "r"(bf[ks][nt][1]));
                }
            }
            // ---- epilogue: relu(C) @ W2, reduce over quad (k2) ----
            float a00 = 0.f, a01 = 0.f, a10 = 0.f, a11 = 0.f;
#pragma unroll
            for (int nt = 0; nt < 8; nt++) {
                float4 w2v = *(const float4*)(s_w2 + (nt * 8 + bk) * 2);
                float r0 = fmaxf(c[nt][0], 0.f), r1 = fmaxf(c[nt][1], 0.f);
                float r2 = fmaxf(c[nt][2], 0.f), r3 = fmaxf(c[nt][3], 0.f);
                a00 = fmaf(r0, w2v.x, fmaf(r1, w2v.z, a00));
                a01 = fmaf(r0, w2v.y, fmaf(r1, w2v.w, a01));
                a10 = fmaf(r2, w2v.x, fmaf(r3, w2v.z, a10));
                a11 = fmaf(r2, w2v.y, fmaf(r3, w2v.w, a11));
            }
            a00 += __shfl_xor_sync(0xffffffffu, a00, 1);
            a00 += __shfl_xor_sync(0xffffffffu, a00, 2);
            a01 += __shfl_xor_sync(0xffffffffu, a01, 1);
            a01 += __shfl_xor_sync(0xffffffffu, a01, 2);
            a10 += __shfl_xor_sync(0xffffffffu, a10, 1);
            a10 += __shfl_xor_sync(0xffffffffu, a10, 2);
            a11 += __shfl_xor_sync(0xffffffffu, a11, 1);
            a11 += __shfl_xor_sync(0xffffffffu, a11, 2);
            if ((lane & 3) == 0) {
                int gg = lane >> 2;
                int base = (bg * 1024 + i) * 2 * 128;
                g_bias[base + j0 + gg]           = a00 + b2_0;
                g_bias[base + 128 + j0 + gg]     = a01 + b2_1;
                g_bias[base + j0 + gg + 8]       = a10 + b2_0;
                g_bias[base + 128 + j0 + gg + 8] = a11 + b2_1;
            }
        }
        __syncthreads();
    }
}

// ---------------- K6b: sim + bias + softmax + attn@V ----------------
#define B_KT   0                         // 128*132 (K transposed, [j][d])
#define B_V    (B_KT + 128 * 132)        // 128*132 ([o][j])
#define B_QC   (B_V + 128 * 132)         // 256
#define B_AT   (B_QC + 256)              // 512
#define B_RD   (B_AT + 512)              // 32
#define B_FLOATS (B_RD + 32)
#define B_BYTES  (B_FLOATS * 4)

__global__ void __launch_bounds__(256, 1) k_attn(int dummy) {
    extern __shared__ float sm[];
    float* s_kt = sm + B_KT;
    float* s_v  = sm + B_V;
    float* s_qc = sm + B_QC;
    float* s_at = sm + B_AT;
    float* s_rd = sm + B_RD;

    int bid = blockIdx.x;
    int bg = bid >> 6;
    int itile = bid & 63;
    int b = bg >> 2, g = bg & 3;
    int tid = threadIdx.x;
    int hf = tid >> 7;
    int j = tid & 127;
    int warp = tid >> 5;

    for (int t = tid; t < 16384; t += 256) {
        int d = t >> 7, jj = t & 127;
        s_kt[jj * 132 + d] = g_k[bg * 16384 + t];
        s_v[d * 132 + jj]  = g_v[bg * 16384 + t];
    }
    __syncthreads();

    const float4* ktp = (const float4*)(s_kt + j * 132);

    for (int it = 0; it < 8; it++) {
        int i = itile * 16 + it * 2 + hf;
        s_qc[tid] = g_q[(bg * 128 + j) * 1024 + i] * 0.125f;
        float bias0 = g_bias[((bg * 1024 + i) * 2 + 0) * 128 + j];
        float bias1 = g_bias[((bg * 1024 + i) * 2 + 1) * 128 + j];
        __syncthreads();

        const float4* qcp = (const float4*)(s_qc + hf * 128);
        float sim0 = bias0, sim1 = bias1;
#pragma unroll
        for (int d4 = 0; d4 < 16; d4++) {
            float4 kq = ktp[d4], qq = qcp[d4];
            sim0 = fmaf(qq.x, kq.x, sim0);
            sim0 = fmaf(qq.y, kq.y, sim0);
            sim0 = fmaf(qq.z, kq.z, sim0);
            sim0 = fmaf(qq.w, kq.w, sim0);
        }
#pragma unroll
        for (int d4 = 16; d4 < 32; d4++) {
            float4 kq = ktp[d4], qq = qcp[d4];
            sim1 = fmaf(qq.x, kq.x, sim1);
            sim1 = fmaf(qq.y, kq.y, sim1);
            sim1 = fmaf(qq.z, kq.z, sim1);
            sim1 = fmaf(qq.w, kq.w, sim1);
        }

        float m0 = sim0, m1 = sim1;
#pragma unroll
        for (int o = 16; o; o >>= 1) {
            m0 = fmaxf(m0, __shfl_xor_sync(0xffffffffu, m0, o));
            m1 = fmaxf(m1, __shfl_xor_sync(0xffffffffu, m1, o));
        }
        if ((tid & 31) == 0) { s_rd[warp] = m0; s_rd[8 + warp] = m1; }
        __syncthreads();
        int hb = hf * 4;
        m0 = fmaxf(fmaxf(s_rd[hb], s_rd[hb + 1]), fmaxf(s_rd[hb + 2], s_rd[hb + 3]));
        m1 = fmaxf(fmaxf(s_rd[8 + hb], s_rd[8 + hb + 1]), fmaxf(s_rd[8 + hb + 2], s_rd[8 + hb + 3]));
        float e0 = __expf(sim0 - m0);
        float e1 = __expf(sim1 - m1);
        float t0 = e0, t1 = e1;
#pragma unroll
        for (int o = 16; o; o >>= 1) {
            t0 += __shfl_xor_sync(0xffffffffu, t0, o);
            t1 += __shfl_xor_sync(0xffffffffu, t1, o);
        }
        if ((tid & 31) == 0) { s_rd[16 + warp] = t0; s_rd[24 + warp] = t1; }
        __syncthreads();
        float sum0 = s_rd[16 + hb] + s_rd[16 + hb + 1] + s_rd[16 + hb + 2] + s_rd[16 + hb + 3];
        float sum1 = s_rd[24 + hb] + s_rd[24 + hb + 1] + s_rd[24 + hb + 2] + s_rd[24 + hb + 3];
        s_at[hf * 256 + j] = e0 / sum0;
        s_at[hf * 256 + 128 + j] = e1 / sum1;
        __syncthreads();

        int row = j;
        const float4* vp = (const float4*)(s_v + row * 132);
        const float4* ap = (const float4*)(s_at + hf * 256 + (row >> 6) * 128);
        float oacc = 0.f;
#pragma unroll
        for (int j4 = 0; j4 < 32; j4++) {
            float4 av = ap[j4], vv = vp[j4];
            oacc = fmaf(av.x, vv.x, oacc);
            oacc = fmaf(av.y, vv.y, oacc);
            oacc = fmaf(av.z, vv.z, oacc);
            oacc = fmaf(av.w, vv.w, oacc);
        }
        g_att[(b * 512 + g * 128 + row) * 1024 + i] = oacc;
        __syncthreads();
    }
}

// ---------------- K7: final projection ----------------
__global__ void __launch_bounds__(256) k_proj(const float* __restrict__ wo,
                                              const float* __restrict__ bo,
                                              float* __restrict__ out) {
    __shared__ float s_wo[16 * 512];
    int bid = blockIdx.x;
    int pt = bid & 3;
    int og = (bid >> 2) & 15;
    int b = bid >> 6;
    int tid = threadIdx.x;
    for (int t = tid; t < 16 * 512; t += 256) {
        int u = t & 15;
        int c = t >> 4;
        s_wo[c * 16 + u] = wo[(og * 16 + u) * 512 + c];
    }
    __syncthreads();
    int p = pt * 256 + tid;
    const float* arow = g_att + b * 512 * 1024 + p;
    ull acc[8];
#pragma unroll
    for (int m = 0; m < 8; m++) acc[m] = 0ull;
#pragma unroll 4
    for (int c = 0; c < 512; c++) {
        float a = arow[c * 1024];
        ull ap = pk2(a, a);
        const ulonglong2* wr = (const ulonglong2*)(s_wo + c * 16);
#pragma unroll
        for (int m = 0; m < 4; m++) {
            ulonglong2 wv2 = wr[m];
            acc[2 * m]     = ffma2(ap, wv2.x, acc[2 * m]);
            acc[2 * m + 1] = ffma2(ap, wv2.y, acc[2 * m + 1]);
        }
    }
#pragma unroll
    for (int m = 0; m < 8; m++) {
        float lo, hi; upk2(acc[m], lo, hi);
        int u = 2 * m;
        out[(b * 256 + og * 16 + u) * 1024 + p] = lo + bo[og * 16 + u];
        out[(b * 256 + og * 16 + u + 1) * 1024 + p] = hi + bo[og * 16 + u + 1];
    }
}

// ---------------- launch ----------------
extern "C" void kernel_launch(void* const* d_in, const int* in_sizes, int n_in,
                              void* d_out, int out_size) {
    const float* x   = (const float*)d_in[0];
    const float* wq  = (const float*)d_in[1];
    const float* wk  = (const float*)d_in[2];
    const float* wv  = (const float*)d_in[3];
    const float* dww = (const float*)d_in[4];
    const float* dwb = (const float*)d_in[5];
    const float* pw  = (const float*)d_in[6];
    const float* w0  = (const float*)d_in[7];
    const float* b0  = (const float*)d_in[8];
    const float* w1  = (const float*)d_in[9];
    const float* b1  = (const float*)d_in[10];
    const float* w2  = (const float*)d_in[11];
    const float* b2  = (const float*)d_in[12];
    const float* wo  = (const float*)d_in[13];
    const float* bo  = (const float*)d_in[14];
    float* out = (float*)d_out;

    cudaFuncSetAttribute(k_attn, cudaFuncAttributeMaxDynamicSharedMemorySize, B_BYTES);

    k_q<<<dim3(NBG, 8, 4), 128>>>(x, wq);
    k_dw<<<(NBG * 128 * PJ + 255) / 256, 256>>>(dww, dwb);
    k_off<<<(NBG * PJ + 255) / 256, 256>>>(pw);
    k_sample<<<(NBG * CG * PJ + 255) / 256, 256>>>(x);
    k_kv<<<dim3(NBG, 4, 2), 128>>>(wk, wv);
    k_bias_mma<<<NBG * 128, 128>>>(w0, b0, w1, b1, w2, b2);
    k_attn<<<NBG * 64, 256, B_BYTES>>>(0);
    k_proj<<<NB * 16 * 4, 256>>>(wo, bo, out);
}

// round 6
// speedup vs baseline: 2.5388x; 1.1883x over previous
#include <cuda_runtime.h>
#include <cuda_bf16.h>
#include <math.h>
#include <stdint.h>

// ---------------- problem constants ----------------
#define NB    2
#define NG    4
#define NBG   8          // NB*NG
#define PQ    1024       // 4*16*16
#define PJ    128        // 2*8*8
#define CG    64         // DIM/GROUPS

// ---------------- scratch ----------------
__device__ float g_q[NBG * 128 * PQ];     // [bg][o][p]
__device__ float g_qt[NBG * PQ * 128];    // [bg][p][o], pre-scaled by 1/8
__device__ float g_dw[NBG * 128 * PJ];    // [bg][c][j]
__device__ float g_grid[NBG * PJ * 3];    // [bg][j][3]
__device__ float g_kv[NBG * CG * PJ];     // [bg][i][j]
__device__ float g_k[NBG * 128 * PJ];     // [bg][o][j]
__device__ float g_v[NBG * 128 * PJ];
__device__ float g_bias[NBG * PQ * 2 * PJ]; // [bg][i][hpg][j]
__device__ float g_att[NB * 512 * PQ];    // [b][c][p]

// ---------------- helpers ----------------
typedef unsigned long long ull;
__device__ __forceinline__ ull pk2(float lo, float hi) {
    ull r; asm("mov.b64 %0, {%1, %2};" : "=l"(r) : "f"(lo), "f"(hi)); return r;
}
__device__ __forceinline__ void upk2(ull v, float& lo, float& hi) {
    asm("mov.b64 {%0, %1}, %2;" : "=f"(lo), "=f"(hi) : "l"(v));
}
__device__ __forceinline__ ull ffma2(ull a, ull b, ull c) {
    ull d; asm("fma.rn.f32x2 %0, %1, %2, %3;" : "=l"(d) : "l"(a), "l"(b), "l"(c)); return d;
}
__device__ __forceinline__ uint32_t pkbf(float lo, float hi) {
    uint32_t r; asm("cvt.rn.bf16x2.f32 %0, %1, %2;" : "=r"(r) : "f"(hi), "f"(lo)); return r;
}
__device__ __forceinline__ uint32_t smaddr(const void* p) {
    uint32_t a;
    asm("{ .reg .u64 t; cvta.to.shared.u64 t, %1; cvt.u32.u64 %0, t; }" : "=r"(a) : "l"(p));
    return a;
}

// ---------------- K1: grouped 1x1 conv -> q (+ transposed prescaled copy) ----------------
__global__ void __launch_bounds__(128) k_q(const float* __restrict__ x,
                                           const float* __restrict__ wq) {
    __shared__ float swt[64][36];
    __shared__ float s_tr[32][129];
    int bg = blockIdx.x, pt = blockIdx.y, oc = blockIdx.z;
    int b = bg >> 2, g = bg & 3;
    int tid = threadIdx.x;
    for (int t = tid; t < 2048; t += 128) {
        int o = t >> 6, i = t & 63;
        swt[i][o] = wq[g * 8192 + (oc * 32 + o) * 64 + i];
    }
    __syncthreads();
    int p = pt * 128 + tid;
    float xr[64];
#pragma unroll
    for (int i = 0; i < 64; i++) xr[i] = x[(b * 256 + g * 64 + i) * 1024 + p];
    ull acc[16];
#pragma unroll
    for (int c = 0; c < 16; c++) acc[c] = 0ull;
#pragma unroll 8
    for (int i = 0; i < 64; i++) {
        ull xp = pk2(xr[i], xr[i]);
        const ulonglong2* wr = (const ulonglong2*)(&swt[i][0]);
#pragma unroll
        for (int m = 0; m < 8; m++) {
            ulonglong2 w = wr[m];
            acc[2 * m]     = ffma2(xp, w.x, acc[2 * m]);
            acc[2 * m + 1] = ffma2(xp, w.y, acc[2 * m + 1]);
        }
    }
#pragma unroll
    for (int c = 0; c < 16; c++) {
        float lo, hi; upk2(acc[c], lo, hi);
        int o = oc * 32 + 2 * c;
        g_q[(bg * 128 + o) * 1024 + p] = lo;
        g_q[(bg * 128 + o + 1) * 1024 + p] = hi;
        s_tr[2 * c][tid] = lo;
        s_tr[2 * c + 1][tid] = hi;
    }
    __syncthreads();
    for (int t = tid; t < 4096; t += 128) {
        int o = t & 31, pp = t >> 5;
        g_qt[(bg * 1024 + pt * 128 + pp) * 128 + oc * 32 + o] = s_tr[o][pp] * 0.125f;
    }
}

// ---------------- K2: depthwise strided conv + bias + exact GELU ----------------
__global__ void __launch_bounds__(256) k_dw(const float* __restrict__ w,
                                            const float* __restrict__ bias) {
    int idx = blockIdx.x * blockDim.x + threadIdx.x;
    if (idx >= NBG * 128 * PJ) return;
    int j = idx & 127;
    int c = (idx >> 7) & 127;
    int bg = idx >> 14;
    int zo = j >> 6, yo = (j >> 3) & 7, xo = j & 7;
    const float* qb = g_q + (bg * 128 + c) * 1024;
    const float* wc = w + c * 64;
    float acc = 0.f;
#pragma unroll
    for (int kz = 0; kz < 4; kz++) {
        int zi = zo * 2 - 1 + kz;
        if (zi < 0 || zi >= 4) continue;
#pragma unroll
        for (int ky = 0; ky < 4; ky++) {
            int yi = yo * 2 - 1 + ky;
            if (yi < 0 || yi >= 16) continue;
#pragma unroll
            for (int kx = 0; kx < 4; kx++) {
                int xi = xo * 2 - 1 + kx;
                if (xi < 0 || xi >= 16) continue;
                acc = fmaf(qb[(zi * 16 + yi) * 16 + xi], wc[(kz * 4 + ky) * 4 + kx], acc);
            }
        }
    }
    acc += bias[c];
    float ge = 0.5f * acc * (1.f + erff(acc * 0.70710678118654752f));
    g_dw[idx] = ge;
}

// ---------------- K3: pointwise -> tanh -> offsets -> normalized grid ----------------
__global__ void __launch_bounds__(256) k_off(const float* __restrict__ pw) {
    int idx = blockIdx.x * blockDim.x + threadIdx.x;
    if (idx >= NBG * PJ) return;
    int j = idx & 127;
    int bg = idx >> 7;
    float a0 = 0.f, a1 = 0.f, a2 = 0.f;
#pragma unroll 8
    for (int c = 0; c < 128; c++) {
        float v = g_dw[(bg * 128 + c) * 128 + j];
        a0 = fmaf(v, pw[c], a0);
        a1 = fmaf(v, pw[128 + c], a1);
        a2 = fmaf(v, pw[256 + c], a2);
    }
    float o0 = tanhf(a0) * 2.f, o1 = tanhf(a1) * 2.f, o2 = tanhf(a2) * 2.f;
    int fz = j >> 6, hy = (j >> 3) & 7, wx = j & 7;
    float v0 = (float)fz + o0, v1 = (float)hy + o1, v2 = (float)wx + o2;
    g_grid[idx * 3 + 0] = 2.f * v0 - 1.f;
    g_grid[idx * 3 + 1] = 2.f * v1 / 7.f - 1.f;
    g_grid[idx * 3 + 2] = 2.f * v2 / 7.f - 1.f;
}

// ---------------- K4: trilinear grid sample ----------------
__global__ void __launch_bounds__(256) k_sample(const float* __restrict__ x) {
    int idx = blockIdx.x * blockDim.x + threadIdx.x;
    if (idx >= NBG * CG * PJ) return;
    int j = idx & 127;
    int c = (idx >> 7) & 63;
    int bg = idx >> 13;
    int b = bg >> 2, g = bg & 3;
    const float* gr = g_grid + (bg * 128 + j) * 3;
    float n0 = gr[0], n1 = gr[1], n2 = gr[2];
    float ix = ((n0 + 1.f) * 16.f - 1.f) * 0.5f;
    float iy = ((n1 + 1.f) * 16.f - 1.f) * 0.5f;
    float iz = ((n2 + 1.f) * 4.f - 1.f) * 0.5f;
    float x0f = floorf(ix), y0f = floorf(iy), z0f = floorf(iz);
    float tx = ix - x0f, ty = iy - y0f, tz = iz - z0f;
    const float* vol = x + (b * 256 + g * 64 + c) * 1024;
    float acc = 0.f;
#pragma unroll
    for (int dz = 0; dz < 2; dz++)
#pragma unroll
        for (int dy = 0; dy < 2; dy++)
#pragma unroll
            for (int dx = 0; dx < 2; dx++) {
                float xc = x0f + dx, yc = y0f + dy, zc = z0f + dz;
                float wgt = (dx ? tx : 1.f - tx) * (dy ? ty : 1.f - ty) * (dz ? tz : 1.f - tz);
                if (xc >= 0.f && xc < 16.f && yc >= 0.f && yc < 16.f && zc >= 0.f && zc < 4.f) {
                    int xi = (int)xc, yi = (int)yc, zi = (int)zc;
                    acc = fmaf(vol[(zi * 16 + yi) * 16 + xi], wgt, acc);
                }
            }
    g_kv[(bg * 64 + c) * 128 + j] = acc;
}

// ---------------- K5: k and v projections ----------------
__global__ void __launch_bounds__(128) k_kv(const float* __restrict__ wk,
                                            const float* __restrict__ wv) {
    __shared__ float swt[64][36];
    int bg = blockIdx.x, oc = blockIdx.y, sel = blockIdx.z;
    int g = bg & 3;
    int tid = threadIdx.x;
    const float* w = sel ? wv : wk;
    float* outp = sel ? g_v : g_k;
    for (int t = tid; t < 2048; t += 128) {
        int o = t >> 6, i = t & 63;
        swt[i][o] = w[g * 8192 + (oc * 32 + o) * 64 + i];
    }
    __syncthreads();
    float kr[64];
#pragma unroll
    for (int i = 0; i < 64; i++) kr[i] = g_kv[(bg * 64 + i) * 128 + tid];
    ull acc[16];
#pragma unroll
    for (int c = 0; c < 16; c++) acc[c] = 0ull;
#pragma unroll 8
    for (int i = 0; i < 64; i++) {
        ull xp = pk2(kr[i], kr[i]);
        const ulonglong2* wr = (const ulonglong2*)(&swt[i][0]);
#pragma unroll
        for (int m = 0; m < 8; m++) {
            ulonglong2 ww = wr[m];
            acc[2 * m]     = ffma2(xp, ww.x, acc[2 * m]);
            acc[2 * m + 1] = ffma2(xp, ww.y, acc[2 * m + 1]);
        }
    }
#pragma unroll
    for (int c = 0; c < 16; c++) {
        float lo, hi; upk2(acc[c], lo, hi);
        int o = oc * 32 + 2 * c;
        outp[(bg * 128 + o) * 128 + tid] = lo;
        outp[(bg * 128 + o + 1) * 128 + tid] = hi;
    }
}

// ---------------- K6a: CPB bias MLP with bf16 HMMA + hoisted base ----------------
// CTA: 128 threads (4 warps), 8 consecutive i's (f, h constant; only w varies).
// base[j][k1] = s0*w0a + s1*w0b + b0 computed ONCE per CTA.
// dynamic smem layout (bytes):
#define C_HB    0                          // 16384 (H bf16, swizzled)
#define C_BASE  16384                      // 128*68*4 = 34816 (stride 68 -> conflict-free)
#define C_W0    (C_BASE + 34816)           // 192 floats
#define C_B0    (C_W0 + 768)               // 64 floats
#define C_W2    (C_B0 + 256)               // 128 floats
#define CB_BYTES (C_W2 + 512)

__global__ void __launch_bounds__(128) k_bias_mma(
    const float* __restrict__ cw0, const float* __restrict__ cb0,
    const float* __restrict__ cw1, const float* __restrict__ cb1,
    const float* __restrict__ cw2, const float* __restrict__ cb2) {
    extern __shared__ char smc[];
    char*  s_Hb   = smc + C_HB;
    float* s_base = (float*)(smc + C_BASE);
    float* s_w0   = (float*)(smc + C_W0);
    float* s_b0   = (float*)(smc + C_B0);
    float* s_w2   = (float*)(smc + C_W2);

    int bid = blockIdx.x;
    int bg = bid >> 7;
    int ibase = (bid & 127) * 8;
    int tid = threadIdx.x;
    int lane = tid & 31;
    int warp = tid >> 5;

    if (tid < 128) s_w0[tid] = cw0[tid];
    if (tid < 64) {
        s_w0[128 + tid] = cw0[128 + tid];
        s_b0[tid] = cb0[tid];
    }
    if (tid < 128) s_w2[tid] = cw2[tid];
    float b2_0 = cb2[0], b2_1 = cb2[1];

    // W1 fragments in registers (invariant)
    int bk = (lane & 3) * 2;
    int bn = lane >> 2;
    uint32_t bf[4][8][2];
#pragma unroll
    for (int ks = 0; ks < 4; ks++)
#pragma unroll
        for (int nt = 0; nt < 8; nt++) {
            int n = nt * 8 + bn;
            int k0 = ks * 16 + bk;
            bf[ks][nt][0] = pkbf(cw1[k0 * 64 + n],       cw1[(k0 + 1) * 64 + n]);
            bf[ks][nt][1] = pkbf(cw1[(k0 + 8) * 64 + n], cw1[(k0 + 9) * 64 + n]);
        }
    float bv0[8], bv1[8];
#pragma unroll
    for (int nt = 0; nt < 8; nt++) {
        bv0[nt] = cb1[nt * 8 + bk];
        bv1[nt] = cb1[nt * 8 + bk + 1];
    }

    // grid coords for j = tid
    float gk0 = g_grid[(bg * 128 + tid) * 3 + 0];
    float gk1 = g_grid[(bg * 128 + tid) * 3 + 1];
    float gk2 = g_grid[(bg * 128 + tid) * 3 + 2];

    uint32_t hbase = smaddr(s_Hb);
    __syncthreads();

    // ---- base build (once per CTA; f and h are constant across the 8 i's) ----
    {
        int fi = ibase >> 8, hy = (ibase >> 4) & 15;
        float p0 = (2.f * (float)fi / 3.f - 1.f) - gk0;
        float p1 = (2.f * (float)hy / 15.f - 1.f) - gk1;
        float s0 = copysignf(log1pf(fabsf(p0)), p0);
        float s1 = copysignf(log1pf(fabsf(p1)), p1);
        float* brow = s_base + tid * 68;
#pragma unroll
        for (int m = 0; m < 8; m++) {
            int k = m * 8;
            float4 wa0 = *(const float4*)(s_w0 + k);
            float4 wa1 = *(const float4*)(s_w0 + k + 4);
            float4 wb0 = *(const float4*)(s_w0 + 64 + k);
            float4 wb1 = *(const float4*)(s_w0 + 64 + k + 4);
            float4 bb0 = *(const float4*)(s_b0 + k);
            float4 bb1 = *(const float4*)(s_b0 + k + 4);
            float4 r0, r1;
            r0.x = fmaf(s0, wa0.x, fmaf(s1, wb0.x, bb0.x));
            r0.y = fmaf(s0, wa0.y, fmaf(s1, wb0.y, bb0.y));
            r0.z = fmaf(s0, wa0.z, fmaf(s1, wb0.z, bb0.z));
            r0.w = fmaf(s0, wa0.w, fmaf(s1, wb0.w, bb0.w));
            r1.x = fmaf(s0, wa1.x, fmaf(s1, wb1.x, bb1.x));
            r1.y = fmaf(s0, wa1.y, fmaf(s1, wb1.y, bb1.y));
            r1.z = fmaf(s0, wa1.z, fmaf(s1, wb1.z, bb1.z));
            r1.w = fmaf(s0, wa1.w, fmaf(s1, wb1.w, bb1.w));
            *(float4*)(brow + k) = r0;
            *(float4*)(brow + k + 4) = r1;
        }
    }
    __syncthreads();

    for (int ii = 0; ii < 8; ii++) {
        int i = ibase + ii;
        int wx = i & 15;
        float p2 = (2.f * (float)wx / 15.f - 1.f) - gk2;
        float s2 = copysignf(log1pf(fabsf(p2)), p2);

        // ---- H row j=tid: h = relu(base + s2*w0c) ----
        {
            int rowoff = tid * 128;
            int swz = (tid & 7) << 4;
            const float* brow = s_base + tid * 68;
#pragma unroll
            for (int m = 0; m < 8; m++) {
                int k = m * 8;
                float4 b4a = *(const float4*)(brow + k);
                float4 b4b = *(const float4*)(brow + k + 4);
                float4 wc0 = *(const float4*)(s_w0 + 128 + k);
                float4 wc1 = *(const float4*)(s_w0 + 128 + k + 4);
                float h0 = fmaxf(fmaf(s2, wc0.x, b4a.x), 0.f);
                float h1 = fmaxf(fmaf(s2, wc0.y, b4a.y), 0.f);
                float h2 = fmaxf(fmaf(s2, wc0.z, b4a.z), 0.f);
                float h3 = fmaxf(fmaf(s2, wc0.w, b4a.w), 0.f);
                float h4 = fmaxf(fmaf(s2, wc1.x, b4b.x), 0.f);
                float h5 = fmaxf(fmaf(s2, wc1.y, b4b.y), 0.f);
                float h6 = fmaxf(fmaf(s2, wc1.z, b4b.z), 0.f);
                float h7 = fmaxf(fmaf(s2, wc1.w, b4b.w), 0.f);
                uint4 st;
                st.x = pkbf(h0, h1); st.y = pkbf(h2, h3);
                st.z = pkbf(h4, h5); st.w = pkbf(h6, h7);
                *(uint4*)(s_Hb + rowoff + ((m * 16) ^ swz)) = st;
            }
        }
        __syncthreads();

        // ---- 2 j-tiles per warp ----
#pragma unroll
        for (int jt2 = 0; jt2 < 2; jt2++) {
            int jt = warp + jt2 * 4;
            int j0 = jt * 16;
            float c[8][4];
#pragma unroll
            for (int nt = 0; nt < 8; nt++) {
                c[nt][0] = bv0[nt]; c[nt][1] = bv1[nt];
                c[nt][2] = bv0[nt]; c[nt][3] = bv1[nt];
            }
#pragma unroll
            for (int ks = 0; ks < 4; ks++) {
                int row = j0 + (lane & 15);
                int colb = ks * 32 + ((lane & 16) ? 16 : 0);
                uint32_t addr = hbase + row * 128 + (colb ^ ((row & 7) << 4));
                uint32_t a0, a1, a2, a3;
                asm volatile("ldmatrix.sync.aligned.m8n8.x4.shared.b16 {%0,%1,%2,%3}, [%4];"
                             : "=r"(a0), "=r"(a1), "=r"(a2), "=r"(a3) : "r"(addr));
#pragma unroll
                for (int nt = 0; nt < 8; nt++) {
                    asm volatile("mma.sync.aligned.m16n8k16.row.col.f32.bf16.bf16.f32 "
                                 "{%0,%1,%2,%3}, {%4,%5,%6,%7}, {%8,%9}, {%0,%1,%2,%3};"
                                 : "+f"(c[nt][0]), "+f"(c[nt][1]), "+f"(c[nt][2]), "+f"(c[nt][3])
                                 : "r"(a0), "r"(a1), "r"(a2), "r"(a3),
                                   "r"(bf[ks][nt][0]), "r"(bf[ks][nt][1]));
                }
            }
            // epilogue: relu(C) @ W2, quad reduce
            float a00 = 0.f, a01 = 0.f, a10 = 0.f, a11 = 0.f;
#pragma unroll
            for (int nt = 0; nt < 8; nt++) {
                float4 w2v = *(const float4*)(s_w2 + (nt * 8 + bk) * 2);
                float r0 = fmaxf(c[nt][0], 0.f), r1 = fmaxf(c[nt][1], 0.f);
                float r2 = fmaxf(c[nt][2], 0.f), r3 = fmaxf(c[nt][3], 0.f);
                a00 = fmaf(r0, w2v.x, fmaf(r1, w2v.z, a00));
                a01 = fmaf(r0, w2v.y, fmaf(r1, w2v.w, a01));
                a10 = fmaf(r2, w2v.x, fmaf(r3, w2v.z, a10));
                a11 = fmaf(r2, w2v.y, fmaf(r3, w2v.w, a11));
            }
            a00 += __shfl_xor_sync(0xffffffffu, a00, 1);
            a00 += __shfl_xor_sync(0xffffffffu, a00, 2);
            a01 += __shfl_xor_sync(0xffffffffu, a01, 1);
            a01 += __shfl_xor_sync(0xffffffffu, a01, 2);
            a10 += __shfl_xor_sync(0xffffffffu, a10, 1);
            a10 += __shfl_xor_sync(0xffffffffu, a10, 2);
            a11 += __shfl_xor_sync(0xffffffffu, a11, 1);
            a11 += __shfl_xor_sync(0xffffffffu, a11, 2);
            if ((lane & 3) == 0) {
                int gg = lane >> 2;
                int base = (bg * 1024 + i) * 2 * 128;
                g_bias[base + j0 + gg]           = a00 + b2_0;
                g_bias[base + 128 + j0 + gg]     = a01 + b2_1;
                g_bias[base + j0 + gg + 8]       = a10 + b2_0;
                g_bias[base + 128 + j0 + gg + 8] = a11 + b2_1;
            }
        }
        __syncthreads();
    }
}

// ---------------- K6b: sim + bias + softmax + attn@V (4 i's per pass per half) ----------------
#define B_KT   0                         // 128*132 (K transposed, [j][d])
#define B_V    (B_KT + 128 * 132)        // 128*132 ([o][j])
#define B_QC   (B_V + 128 * 132)         // 1024 (8 i x 128 d)
#define B_AT   (B_QC + 1024)             // 2048 (hf,ii,head,j)
#define B_RD   (B_AT + 2048)             // 128
#define B_FLOATS (B_RD + 128)
#define B_BYTES  (B_FLOATS * 4)

__global__ void __launch_bounds__(256, 1) k_attn(int dummy) {
    extern __shared__ float sm[];
    float* s_kt = sm + B_KT;
    float* s_v  = sm + B_V;
    float* s_qc = sm + B_QC;
    float* s_at = sm + B_AT;
    float* s_rd = sm + B_RD;

    int bid = blockIdx.x;
    int bg = bid >> 6;
    int itile = bid & 63;
    int b = bg >> 2, g = bg & 3;
    int tid = threadIdx.x;
    int hf = tid >> 7;
    int j = tid & 127;
    int warp = tid >> 5;
    int wih = warp & 3;
    int head = j >> 6;

    for (int t = tid; t < 16384; t += 256) {
        int d = t >> 7, jj = t & 127;
        s_kt[jj * 132 + d] = g_k[bg * 16384 + t];
        s_v[d * 132 + jj]  = g_v[bg * 16384 + t];
    }
    __syncthreads();

    const float4* ktp = (const float4*)(s_kt + j * 132);
    const float4* vp  = (const float4*)(s_v + j * 132);

    for (int ps = 0; ps < 2; ps++) {
        int i0 = itile * 16 + ps * 8;
        // stage q (coalesced from transposed, prescaled g_qt)
        for (int t = tid; t < 1024; t += 256)
            s_qc[t] = g_qt[(bg * 1024 + i0 + (t >> 7)) * 128 + (t & 127)];
        // bias for this half's 4 i's
        float sim[4][2];
#pragma unroll
        for (int ii = 0; ii < 4; ii++) {
            int i = i0 + hf * 4 + ii;
            sim[ii][0] = g_bias[((bg * 1024 + i) * 2 + 0) * 128 + j];
            sim[ii][1] = g_bias[((bg * 1024 + i) * 2 + 1) * 128 + j];
        }
        __syncthreads();

        const float* qb = s_qc + hf * 4 * 128;
#pragma unroll
        for (int d4 = 0; d4 < 16; d4++) {
            float4 k4 = ktp[d4];
#pragma unroll
            for (int ii = 0; ii < 4; ii++) {
                float4 q4 = *(const float4*)(qb + ii * 128 + d4 * 4);
                sim[ii][0] = fmaf(q4.x, k4.x, fmaf(q4.y, k4.y,
                             fmaf(q4.z, k4.z, fmaf(q4.w, k4.w, sim[ii][0]))));
            }
        }
#pragma unroll
        for (int d4 = 16; d4 < 32; d4++) {
            float4 k4 = ktp[d4];
#pragma unroll
            for (int ii = 0; ii < 4; ii++) {
                float4 q4 = *(const float4*)(qb + ii * 128 + d4 * 4);
                sim[ii][1] = fmaf(q4.x, k4.x, fmaf(q4.y, k4.y,
                             fmaf(q4.z, k4.z, fmaf(q4.w, k4.w, sim[ii][1]))));
            }
        }

        // ---- softmax over j (128 threads per half) ----
        float mx[4][2];
#pragma unroll
        for (int ii = 0; ii < 4; ii++)
#pragma unroll
            for (int h = 0; h < 2; h++) {
                float m = sim[ii][h];
#pragma unroll
                for (int o = 16; o; o >>= 1)
                    m = fmaxf(m, __shfl_xor_sync(0xffffffffu, m, o));
                if ((tid & 31) == 0) s_rd[((hf * 4 + ii) * 2 + h) * 4 + wih] = m;
                mx[ii][h] = m;
            }
        __syncthreads();
        float ex[4][2];
#pragma unroll
        for (int ii = 0; ii < 4; ii++)
#pragma unroll
            for (int h = 0; h < 2; h++) {
                const float* rb = s_rd + ((hf * 4 + ii) * 2 + h) * 4;
                float m = fmaxf(fmaxf(rb[0], rb[1]), fmaxf(rb[2], rb[3]));
                float e = __expf(sim[ii][h] - m);
                ex[ii][h] = e;
                float s = e;
#pragma unroll
                for (int o = 16; o; o >>= 1)
                    s += __shfl_xor_sync(0xffffffffu, s, o);
                if ((tid & 31) == 0) s_rd[64 + ((hf * 4 + ii) * 2 + h) * 4 + wih] = s;
            }
        __syncthreads();
#pragma unroll
        for (int ii = 0; ii < 4; ii++)
#pragma unroll
            for (int h = 0; h < 2; h++) {
                const float* rb = s_rd + 64 + ((hf * 4 + ii) * 2 + h) * 4;
                float s = rb[0] + rb[1] + rb[2] + rb[3];
                s_at[((hf * 4 + ii) * 2 + h) * 128 + j] = ex[ii][h] / s;
            }
        __syncthreads();

        // ---- AV: thread owns row j; 4 i's per pass ----
        float oacc[4] = {0.f, 0.f, 0.f, 0.f};
#pragma unroll
        for (int j4 = 0; j4 < 32; j4++) {
            float4 v4 = vp[j4];
#pragma unroll
            for (int ii = 0; ii < 4; ii++) {
                float4 a4 = *(const float4*)(s_at + ((hf * 4 + ii) * 2 + head) * 128 + j4 * 4);
                oacc[ii] = fmaf(a4.x, v4.x, fmaf(a4.y, v4.y,
                           fmaf(a4.z, v4.z, fmaf(a4.w, v4.w, oacc[ii]))));
            }
        }
#pragma unroll
        for (int ii = 0; ii < 4; ii++)
            g_att[(b * 512 + g * 128 + j) * 1024 + i0 + hf * 4 + ii] = oacc[ii];
        __syncthreads();
    }
}

// ---------------- K7: final projection (32 o-groups of 8) ----------------
__global__ void __launch_bounds__(256) k_proj(const float* __restrict__ wo,
                                              const float* __restrict__ bo,
                                              float* __restrict__ out) {
    __shared__ float s_wo[512 * 8];  // [c][u]
    int bid = blockIdx.x;
    int pt = bid & 3;
    int og = (bid >> 2) & 31;
    int b = bid >> 7;
    int tid = threadIdx.x;
    for (int t = tid; t < 4096; t += 256) {
        int u = t & 7;
        int c = t >> 3;
        s_wo[c * 8 + u] = wo[(og * 8 + u) * 512 + c];
    }
    __syncthreads();
    int p = pt * 256 + tid;
    const float* arow = g_att + b * 512 * 1024 + p;
    ull acc[4];
#pragma unroll
    for (int m = 0; m < 4; m++) acc[m] = 0ull;
#pragma unroll 4
    for (int c = 0; c < 512; c++) {
        float a = arow[c * 1024];
        ull ap = pk2(a, a);
        const ulonglong2* wr = (const ulonglong2*)(s_wo + c * 8);
        ulonglong2 w0 = wr[0], w1 = wr[1];
        acc[0] = ffma2(ap, w0.x, acc[0]);
        acc[1] = ffma2(ap, w0.y, acc[1]);
        acc[2] = ffma2(ap, w1.x, acc[2]);
        acc[3] = ffma2(ap, w1.y, acc[3]);
    }
#pragma unroll
    for (int m = 0; m < 4; m++) {
        float lo, hi; upk2(acc[m], lo, hi);
        int u = 2 * m;
        out[(b * 256 + og * 8 + u) * 1024 + p] = lo + bo[og * 8 + u];
        out[(b * 256 + og * 8 + u + 1) * 1024 + p] = hi + bo[og * 8 + u + 1];
    }
}

// ---------------- launch ----------------
extern "C" void kernel_launch(void* const* d_in, const int* in_sizes, int n_in,
                              void* d_out, int out_size) {
    const float* x   = (const float*)d_in[0];
    const float* wq  = (const float*)d_in[1];
    const float* wk  = (const float*)d_in[2];
    const float* wv  = (const float*)d_in[3];
    const float* dww = (const float*)d_in[4];
    const float* dwb = (const float*)d_in[5];
    const float* pw  = (const float*)d_in[6];
    const float* w0  = (const float*)d_in[7];
    const float* b0  = (const float*)d_in[8];
    const float* w1  = (const float*)d_in[9];
    const float* b1  = (const float*)d_in[10];
    const float* w2  = (const float*)d_in[11];
    const float* b2  = (const float*)d_in[12];
    const float* wo  = (const float*)d_in[13];
    const float* bo  = (const float*)d_in[14];
    float* out = (float*)d_out;

    cudaFuncSetAttribute(k_attn, cudaFuncAttributeMaxDynamicSharedMemorySize, B_BYTES);
    cudaFuncSetAttribute(k_bias_mma, cudaFuncAttributeMaxDynamicSharedMemorySize, CB_BYTES);

    k_q<<<dim3(NBG, 8, 4), 128>>>(x, wq);
    k_dw<<<(NBG * 128 * PJ + 255) / 256, 256>>>(dww, dwb);
    k_off<<<(NBG * PJ + 255) / 256, 256>>>(pw);
    k_sample<<<(NBG * CG * PJ + 255) / 256, 256>>>(x);
    k_kv<<<dim3(NBG, 4, 2), 128>>>(wk, wv);
    k_bias_mma<<<NBG * 128, 128, CB_BYTES>>>(w0, b0, w1, b1, w2, b2);
    k_attn<<<NBG * 64, 256, B_BYTES>>>(0);
    k_proj<<<NB * 32 * 4, 256>>>(wo, bo, out);
}